// round 4
// baseline (speedup 1.0000x reference)
#include <cuda_runtime.h>
#include <math.h>

#define T_STEPS 5
#define HID 64
#define LH 128

#define MAX_N 16000
#define MAX_M (T_STEPS*MAX_N)

// ---------------- scratch (device globals; no runtime allocation) ----------------
__device__ float d_deg [MAX_N];
__device__ float d_dinv[MAX_N];
__device__ float d_acc [MAX_N*T_STEPS];
__device__ float d_a   [MAX_M];                 // GCN scalar per (t,node), [t][n]
__device__ float d_y0  [(size_t)MAX_M*LH];      // layer-0 hidden sequence
__device__ float d_hA  [(size_t)MAX_N*LH];
__device__ float d_hB  [(size_t)MAX_N*LH];
__device__ float d_c   [(size_t)MAX_N*LH];
__device__ float d_wt0 [4*6*32*256];            // transformed (dup+permuted) wih0|whh0
__device__ float d_wt1 [4*8*32*256];            // transformed wih1|whh1

typedef unsigned long long u64;

__device__ __forceinline__ float sigm_(float x)  { return __fdividef(1.0f, 1.0f + __expf(-x)); }
__device__ __forceinline__ float tanh_(float x)  { return __fdividef(2.0f, 1.0f + __expf(-2.0f*x)) - 1.0f; }

__device__ __forceinline__ u64 ffma2(u64 a, u64 b, u64 c) {
    u64 d;
    asm("fma.rn.f32x2 %0, %1, %2, %3;" : "=l"(d) : "l"(a), "l"(b), "l"(c));
    return d;
}
__device__ __forceinline__ u64 lds64(unsigned a) {
    u64 v;
    asm volatile("ld.shared.b64 %0, [%1];" : "=l"(v) : "r"(a));
    return v;
}
__device__ __forceinline__ float2 unpack2(u64 v) {
    float2 r;
    asm("mov.b64 {%0, %1}, %2;" : "=f"(r.x), "=f"(r.y) : "l"(v));
    return r;
}
__device__ __forceinline__ void cp16(unsigned d, const float* s) {
    asm volatile("cp.async.cg.shared.global [%0], [%1], 16;" :: "r"(d), "l"(s));
}

// ---------------- GCN scalar pipeline ----------------
__global__ void k_deg_init(float* deg, int n) {
    int i = blockIdx.x*blockDim.x + threadIdx.x;
    if (i < n) deg[i] = 1.0f;
}
__global__ void k_deg_edges(const int* __restrict__ dst, float* deg, int E) {
    int e = blockIdx.x*blockDim.x + threadIdx.x;
    if (e < E) atomicAdd(&deg[dst[e]], 1.0f);
}
__global__ void k_dinv_accinit(const float* __restrict__ x, const float* __restrict__ deg,
                               float* __restrict__ dinv, float* __restrict__ acc, int n) {
    int i = blockIdx.x*blockDim.x + threadIdx.x;
    if (i >= n) return;
    float di = rsqrtf(deg[i]);
    dinv[i] = di;
#pragma unroll
    for (int t = 0; t < T_STEPS; t++)
        acc[i*T_STEPS + t] = x[i*T_STEPS + t] * di;
}
__global__ void k_scatter(const int* __restrict__ src, const int* __restrict__ dst,
                          const float* __restrict__ x, const float* __restrict__ dinv,
                          float* __restrict__ acc, int E) {
    int e = blockIdx.x*blockDim.x + threadIdx.x;
    if (e >= E) return;
    int s = src[e], d = dst[e];
    float ds = dinv[s];
#pragma unroll
    for (int t = 0; t < T_STEPS; t++)
        atomicAdd(&acc[d*T_STEPS + t], x[s*T_STEPS + t] * ds);
}
__global__ void k_afin(const float* __restrict__ acc, const float* __restrict__ dinv,
                       float* __restrict__ a, int NN) {
    int i = blockIdx.x*blockDim.x + threadIdx.x;
    if (i >= NN*T_STEPS) return;
    int n = i % NN, t = i / NN;
    a[i] = acc[n*T_STEPS + t] * dinv[n];
}

// ---------------- weight pre-transform ----------------
// Wt[u0b][ch][k][2*jl{,+1}] = W[(gate*LH + u0b*32 + (jl&31)) , ch_k]   (gate = jl>>5)
// ch < NC1 -> W1 (512 x K1), else W2 (512 x 128). Value duplicated for f32x2 LDS.64.
__global__ void k_prepw(const float* __restrict__ W1, const float* __restrict__ W2,
                        float* __restrict__ Wt, int K1, int NC1, int NC) {
    int idx = blockIdx.x*256 + threadIdx.x;
    int total = 4*NC*32*128;
    if (idx >= total) return;
    int jl  = idx & 127;
    int k   = (idx >> 7) & 31;
    int rest = idx >> 12;
    int ch  = rest % NC;
    int u0b = rest / NC;
    int gate = jl >> 5, u = u0b*32 + (jl & 31);
    float v;
    if (ch < NC1) v = W1[(gate*LH + u)*K1 + ch*32 + k];
    else          v = W2[(gate*LH + u)*LH + (ch - NC1)*32 + k];
    float* dst = Wt + (((size_t)(u0b*NC + ch)*32 + k) * 256) + 2*jl;
    dst[0] = v;
    dst[1] = v;
}

// ---------------- fused LSTM-step GEMM, f32x2 core ----------------
// g = A1@W1^T (+ H@W2^T) + b1 + b2, gate-permuted columns, LSTM epilogue in-register.
// Rows paired into f32x2 accumulators; B duplicated in smem so both operands are
// single LDS.64. Weights stream from the pre-transformed Wt via cp.async,
// double-buffered; A tiles double-buffered via register prefetch + STS transpose.
template<int NC1, bool FEAT, bool HAS_H>
__global__ void __launch_bounds__(256, 2)
k_fused(const float* __restrict__ A1,
        const float* __restrict__ gw, const float* __restrict__ gb,
        const float* __restrict__ Wt, int WtNC,
        const float* __restrict__ Hh,
        const float* __restrict__ b1, const float* __restrict__ b2,
        float* __restrict__ c, float* __restrict__ h_out, int M)
{
    constexpr int NC = NC1 + (HAS_H ? 4 : 0);
    extern __shared__ float sm[];
    float* As0 = sm;                 // [32][130]
    float* As1 = sm + 32*130;
    float* Wb0 = sm + 2*32*130;      // [32][256]
    float* Wb1 = Wb0 + 32*256;

    const int m0  = blockIdx.x*128;
    const int u0b = blockIdx.y;
    const int tid = threadIdx.x;
    const int ty  = tid >> 4, tx = tid & 15;
    const int k4  = tid & 7, r0 = tid >> 3;

    const float* WtB = Wt + (size_t)u0b*WtNC*32*256;

    const unsigned asb0 = (unsigned)__cvta_generic_to_shared(As0);
    const unsigned asb1 = (unsigned)__cvta_generic_to_shared(As1);
    const unsigned wbb0 = (unsigned)__cvta_generic_to_shared(Wb0);
    const unsigned wbb1 = (unsigned)__cvta_generic_to_shared(Wb1);

    float avr[4];
    if (FEAT) {
#pragma unroll
        for (int i = 0; i < 4; i++) avr[i] = A1[m0 + r0 + 32*i];
    }

    auto cpW = [&](int ch, unsigned wbase) {
        const float* src = WtB + (size_t)ch*32*256 + tid*32;
        unsigned dst = wbase + tid*128;
#pragma unroll
        for (int i = 0; i < 8; i++) cp16(dst + 16*i, src + 4*i);
        asm volatile("cp.async.commit_group;");
    };

    float4 pa[4];
    auto ldA = [&](int ch) {
        const float* A; int k0;
        if (ch < NC1) { if (FEAT) return; A = A1; k0 = ch*32; }
        else          { A = Hh; k0 = (ch - NC1)*32; }
#pragma unroll
        for (int i = 0; i < 4; i++)
            pa[i] = *(const float4*)(A + (size_t)(m0 + r0 + 32*i)*LH + k0 + 4*k4);
    };

    auto stsA = [&](int ch, float* dstAs) {
        if (FEAT && ch < NC1) {
            int kg = ch*32 + 4*k4;
            float g0 = gw[kg], g1 = gw[kg+1], g2 = gw[kg+2], g3 = gw[kg+3];
            float h0 = gb[kg], h1 = gb[kg+1], h2 = gb[kg+2], h3 = gb[kg+3];
#pragma unroll
            for (int i = 0; i < 4; i++) {
                int m = r0 + 32*i; float av = avr[i];
                dstAs[(4*k4+0)*130 + m] = fmaxf(fmaf(av, g0, h0), 0.f);
                dstAs[(4*k4+1)*130 + m] = fmaxf(fmaf(av, g1, h1), 0.f);
                dstAs[(4*k4+2)*130 + m] = fmaxf(fmaf(av, g2, h2), 0.f);
                dstAs[(4*k4+3)*130 + m] = fmaxf(fmaf(av, g3, h3), 0.f);
            }
        } else {
#pragma unroll
            for (int i = 0; i < 4; i++) {
                int m = r0 + 32*i;
                dstAs[(4*k4+0)*130 + m] = pa[i].x;
                dstAs[(4*k4+1)*130 + m] = pa[i].y;
                dstAs[(4*k4+2)*130 + m] = pa[i].z;
                dstAs[(4*k4+3)*130 + m] = pa[i].w;
            }
        }
    };

    u64 acc2[4][8];
#pragma unroll
    for (int rp = 0; rp < 4; rp++)
#pragma unroll
        for (int cc = 0; cc < 8; cc++) acc2[rp][cc] = 0ull;

    // prologue: stage chunk 0, prefetch chunk 1's A
    cpW(0, wbb0);
    ldA(0);
    stsA(0, As0);
    if (NC > 1) ldA(1);
    asm volatile("cp.async.wait_group 0;");
    __syncthreads();

#pragma unroll
    for (int ch = 0; ch < NC; ch++) {
        if (ch + 1 < NC) cpW(ch+1, ((ch+1)&1) ? wbb1 : wbb0);
        if (ch + 1 < NC) stsA(ch+1, ((ch+1)&1) ? As1 : As0);
        if (ch + 2 < NC) ldA(ch+2);

        const unsigned ab = ((ch&1) ? asb1 : asb0) + 8*ty;
        const unsigned bb = ((ch&1) ? wbb1 : wbb0) + 8*tx;
#pragma unroll
        for (int k = 0; k < 32; k++) {
            u64 aa[4], bv[8];
#pragma unroll
            for (int rp = 0; rp < 4; rp++) aa[rp] = lds64(ab + k*520 + rp*128);
#pragma unroll
            for (int cc = 0; cc < 8; cc++) bv[cc] = lds64(bb + k*1024 + cc*128);
#pragma unroll
            for (int rp = 0; rp < 4; rp++)
#pragma unroll
                for (int cc = 0; cc < 8; cc++)
                    acc2[rp][cc] = ffma2(aa[rp], bv[cc], acc2[rp][cc]);
        }
        if (ch + 1 < NC) {
            asm volatile("cp.async.wait_group 0;");
            __syncthreads();
        }
    }

    // epilogue: cc = 2*gate + q ; rows = m0 + 2*ty + 32*rp + s
#pragma unroll
    for (int q = 0; q < 2; q++) {
        int u = u0b*32 + tx + 16*q;
        float bi = b1[u]        + b2[u];
        float bf = b1[LH+u]     + b2[LH+u];
        float bg = b1[2*LH+u]   + b2[2*LH+u];
        float bo = b1[3*LH+u]   + b2[3*LH+u];
#pragma unroll
        for (int rp = 0; rp < 4; rp++) {
            float2 vi = unpack2(acc2[rp][0+q]);
            float2 vf = unpack2(acc2[rp][2+q]);
            float2 vg = unpack2(acc2[rp][4+q]);
            float2 vo = unpack2(acc2[rp][6+q]);
#pragma unroll
            for (int s = 0; s < 2; s++) {
                int m = m0 + 2*ty + 32*rp + s;
                if (m >= M) continue;
                float gi = (s ? vi.y : vi.x) + bi;
                float gf = (s ? vf.y : vf.x) + bf;
                float gg = (s ? vg.y : vg.x) + bg;
                float go = (s ? vo.y : vo.x) + bo;
                float cn;
                if (HAS_H) {
                    float co = c[(size_t)m*LH + u];
                    cn = sigm_(gf)*co + sigm_(gi)*tanh_(gg);
                } else {
                    cn = sigm_(gi)*tanh_(gg);
                }
                float hn = sigm_(go)*tanh_(cn);
                c[(size_t)m*LH + u]     = cn;
                h_out[(size_t)m*LH + u] = hn;
            }
        }
    }
}

// ---------------- head: out = x_t + relu(h@pw1^T+pb1)@pw2^T + pb2 ----------------
__global__ void k_head(const float* __restrict__ h, const float* __restrict__ x,
                       const float* __restrict__ pw1, const float* __restrict__ pb1,
                       const float* __restrict__ pw2, const float* __restrict__ pb2,
                       float* __restrict__ out, int NN) {
    __shared__ float w1s[128][65];
    __shared__ float w2s[64], b1s[64];
    const int tid = threadIdx.x;
    for (int idx = tid; idx < 64*128; idx += 256) {
        int j = idx >> 7, k = idx & 127;
        w1s[k][j] = pw1[idx];
    }
    if (tid < 64) { w2s[tid] = pw2[tid]; b1s[tid] = pb1[tid]; }
    __syncthreads();

    int warp = tid >> 5, lane = tid & 31;
    int n = blockIdx.x*8 + warp;
    if (n >= NN) return;
    const float* hr = h + (size_t)n*LH;
    float s0 = b1s[lane], s1 = b1s[lane+32];
#pragma unroll 8
    for (int k = 0; k < 128; k++) {
        float hv = hr[k];
        s0 = fmaf(hv, w1s[k][lane],    s0);
        s1 = fmaf(hv, w1s[k][lane+32], s1);
    }
    float part = fmaxf(s0, 0.f)*w2s[lane] + fmaxf(s1, 0.f)*w2s[lane+32];
#pragma unroll
    for (int o = 16; o; o >>= 1) part += __shfl_xor_sync(0xffffffffu, part, o);
    if (lane == 0) out[n] = part + pb2[0] + x[n*T_STEPS + (T_STEPS-1)];
}

// ---------------- launcher ----------------
extern "C" void kernel_launch(void* const* d_in, const int* in_sizes, int n_in,
                              void* d_out, int out_size) {
    const float* x    = (const float*)d_in[0];
    const int*   ei   = (const int*)  d_in[1];
    const float* gw   = (const float*)d_in[2];
    const float* gb   = (const float*)d_in[3];
    const float* wih0 = (const float*)d_in[4];
    const float* whh0 = (const float*)d_in[5];
    const float* bih0 = (const float*)d_in[6];
    const float* bhh0 = (const float*)d_in[7];
    const float* wih1 = (const float*)d_in[8];
    const float* whh1 = (const float*)d_in[9];
    const float* bih1 = (const float*)d_in[10];
    const float* bhh1 = (const float*)d_in[11];
    const float* pw1  = (const float*)d_in[12];
    const float* pb1  = (const float*)d_in[13];
    const float* pw2  = (const float*)d_in[14];
    const float* pb2  = (const float*)d_in[15];
    float* out = (float*)d_out;

    const int NN = in_sizes[0] / T_STEPS;   // 16000
    const int E  = in_sizes[1] / 2;         // 256000
    const int* src = ei;
    const int* dst = ei + E;

    float *p_deg, *p_dinv, *p_acc, *p_a, *p_y0, *p_hA, *p_hB, *p_c, *p_wt0, *p_wt1;
    cudaGetSymbolAddress((void**)&p_deg,  d_deg);
    cudaGetSymbolAddress((void**)&p_dinv, d_dinv);
    cudaGetSymbolAddress((void**)&p_acc,  d_acc);
    cudaGetSymbolAddress((void**)&p_a,    d_a);
    cudaGetSymbolAddress((void**)&p_y0,   d_y0);
    cudaGetSymbolAddress((void**)&p_hA,   d_hA);
    cudaGetSymbolAddress((void**)&p_hB,   d_hB);
    cudaGetSymbolAddress((void**)&p_c,    d_c);
    cudaGetSymbolAddress((void**)&p_wt0,  d_wt0);
    cudaGetSymbolAddress((void**)&p_wt1,  d_wt1);

    const int SMB = (2*32*130 + 2*32*256) * (int)sizeof(float);   // 98816
    cudaFuncSetAttribute(k_fused<2,true ,false>, cudaFuncAttributeMaxDynamicSharedMemorySize, SMB);
    cudaFuncSetAttribute(k_fused<2,true ,true >, cudaFuncAttributeMaxDynamicSharedMemorySize, SMB);
    cudaFuncSetAttribute(k_fused<4,false,false>, cudaFuncAttributeMaxDynamicSharedMemorySize, SMB);
    cudaFuncSetAttribute(k_fused<4,false,true >, cudaFuncAttributeMaxDynamicSharedMemorySize, SMB);

    // weight pre-transform (dup + gate permute + k-major blocking)
    k_prepw<<<(4*6*32*128 + 255)/256, 256>>>(wih0, whh0, p_wt0, HID, 2, 6);
    k_prepw<<<(4*8*32*128 + 255)/256, 256>>>(wih1, whh1, p_wt1, LH,  4, 8);

    // GCN scalar aggregation -> per-(t,node) scalar d_a
    k_deg_init    <<<(NN + 255)/256, 256>>>(p_deg, NN);
    k_deg_edges   <<<(E  + 255)/256, 256>>>(dst, p_deg, E);
    k_dinv_accinit<<<(NN + 255)/256, 256>>>(x, p_deg, p_dinv, p_acc, NN);
    k_scatter     <<<(E  + 255)/256, 256>>>(src, dst, x, p_dinv, p_acc, E);
    k_afin        <<<(NN*T_STEPS + 255)/256, 256>>>(p_acc, p_dinv, p_a, NN);

    dim3 gS((NN + 127)/128, 4);

    // Layer 0: features built on the fly from GCN scalar (K1=64), recurrent K=128
    k_fused<2,true,false><<<gS, 256, SMB>>>(p_a, gw, gb, p_wt0, 6, nullptr,
                                            bih0, bhh0, p_c, p_y0, NN);
    for (int t = 1; t < T_STEPS; t++)
        k_fused<2,true,true><<<gS, 256, SMB>>>(p_a + (size_t)t*NN, gw, gb, p_wt0, 6,
                                               p_y0 + (size_t)(t-1)*NN*LH,
                                               bih0, bhh0, p_c,
                                               p_y0 + (size_t)t*NN*LH, NN);

    // Layer 1: ih folded (K1=128), recurrent K=128
    k_fused<4,false,false><<<gS, 256, SMB>>>(p_y0, nullptr, nullptr, p_wt1, 8, nullptr,
                                             bih1, bhh1, p_c, p_hA, NN);
    float* hin = p_hA; float* hout = p_hB;
    for (int t = 1; t < T_STEPS; t++) {
        k_fused<4,false,true><<<gS, 256, SMB>>>(p_y0 + (size_t)t*NN*LH, nullptr, nullptr, p_wt1, 8,
                                                hin, bih1, bhh1, p_c, hout, NN);
        float* tmp = hin; hin = hout; hout = tmp;
    }

    // Head + residual
    k_head<<<(NN + 7)/8, 256>>>(hin, x, pw1, pb1, pw2, pb2, out, NN);
}

// round 6
// speedup vs baseline: 3.3341x; 3.3341x over previous
#include <cuda_runtime.h>
#include <cuda_bf16.h>
#include <math.h>
#include <stdint.h>

#define T_STEPS 5
#define HID 64
#define LH 128

#define MAX_N 16000
#define MAX_M (T_STEPS*MAX_N)

// ---------------- scratch (device globals; no runtime allocation) ----------------
__device__ float d_deg [MAX_N];
__device__ float d_dinv[MAX_N];
__device__ float d_acc [MAX_N*T_STEPS];
__device__ float d_a   [MAX_M];                          // GCN scalar per (t,node), [t][n]
__device__ float d_c   [(size_t)MAX_N*LH];               // LSTM cell state (fp32)
__device__ __nv_bfloat16 d_y0b [(size_t)MAX_M*LH];       // layer-0 hidden sequence (bf16)
__device__ __nv_bfloat16 d_hAb [(size_t)MAX_N*LH];
__device__ __nv_bfloat16 d_hBb [(size_t)MAX_N*LH];
__device__ __nv_bfloat16 d_img0[4*128*200];              // weight image layer0: [q][j][k], pitch 200
__device__ __nv_bfloat16 d_img1[4*128*264];              // weight image layer1: pitch 264
__device__ float d_biasC[1024];                          // combined biases: [layer][q][j]

// ---------------- helpers ----------------
__device__ __forceinline__ float tanhfast(float x) {
    float y; asm("tanh.approx.f32 %0, %1;" : "=f"(y) : "f"(x)); return y;
}
__device__ __forceinline__ float sigmfast(float x) { return fmaf(tanhfast(0.5f*x), 0.5f, 0.5f); }

__device__ __forceinline__ uint32_t smem_u32(const void* p) {
    uint32_t a;
    asm("{ .reg .u64 t; cvta.to.shared.u64 t, %1; cvt.u32.u64 %0, t; }" : "=r"(a) : "l"(p));
    return a;
}
__device__ __forceinline__ void cp16(uint32_t d, const void* s) {
    asm volatile("cp.async.cg.shared.global [%0], [%1], 16;" :: "r"(d), "l"(s));
}
__device__ __forceinline__ void ldsm4(uint32_t a, uint32_t& r0, uint32_t& r1, uint32_t& r2, uint32_t& r3) {
    asm volatile("ldmatrix.sync.aligned.m8n8.x4.shared.b16 {%0,%1,%2,%3}, [%4];"
                 : "=r"(r0), "=r"(r1), "=r"(r2), "=r"(r3) : "r"(a));
}
__device__ __forceinline__ void mma16816(float* d, const uint32_t* a, const uint32_t* b) {
    asm volatile("mma.sync.aligned.m16n8k16.row.col.f32.bf16.bf16.f32 "
        "{%0,%1,%2,%3}, {%4,%5,%6,%7}, {%8,%9}, {%0,%1,%2,%3};"
        : "+f"(d[0]), "+f"(d[1]), "+f"(d[2]), "+f"(d[3])
        : "r"(a[0]), "r"(a[1]), "r"(a[2]), "r"(a[3]), "r"(b[0]), "r"(b[1]));
}

// ---------------- GCN scalar pipeline ----------------
__global__ void k_deg_init(float* deg, int n) {
    int i = blockIdx.x*blockDim.x + threadIdx.x;
    if (i < n) deg[i] = 1.0f;
}
__global__ void k_deg_edges(const int* __restrict__ dst, float* deg, int E) {
    int e = blockIdx.x*blockDim.x + threadIdx.x;
    if (e < E) atomicAdd(&deg[dst[e]], 1.0f);
}
__global__ void k_dinv_accinit(const float* __restrict__ x, const float* __restrict__ deg,
                               float* __restrict__ dinv, float* __restrict__ acc, int n) {
    int i = blockIdx.x*blockDim.x + threadIdx.x;
    if (i >= n) return;
    float di = rsqrtf(deg[i]);
    dinv[i] = di;
#pragma unroll
    for (int t = 0; t < T_STEPS; t++)
        acc[i*T_STEPS + t] = x[i*T_STEPS + t] * di;
}
__global__ void k_scatter(const int* __restrict__ src, const int* __restrict__ dst,
                          const float* __restrict__ x, const float* __restrict__ dinv,
                          float* __restrict__ acc, int E) {
    int e = blockIdx.x*blockDim.x + threadIdx.x;
    if (e >= E) return;
    int s = src[e], d = dst[e];
    float ds = dinv[s];
#pragma unroll
    for (int t = 0; t < T_STEPS; t++)
        atomicAdd(&acc[d*T_STEPS + t], x[s*T_STEPS + t] * ds);
}
__global__ void k_afin(const float* __restrict__ acc, const float* __restrict__ dinv,
                       float* __restrict__ a, int NN) {
    int i = blockIdx.x*blockDim.x + threadIdx.x;
    if (i >= NN*T_STEPS) return;
    int n = i % NN, t = i / NN;
    a[i] = acc[n*T_STEPS + t] * dinv[n];
}

// ---------------- weight/bias pre-transform ----------------
// img[q][j][k], j = 4*local_unit + gate (unit = q*32+lu, W row = gate*128+unit),
// k = [ih | hh], pitch KP = Kih+128+8 (pad cols never read).
__global__ void k_prepw_mma(const float* __restrict__ Wih, const float* __restrict__ Whh,
                            __nv_bfloat16* __restrict__ img, int Kih, int KP) {
    int K = Kih + LH;
    int idx = blockIdx.x*256 + threadIdx.x;
    if (idx >= 4*128*K) return;
    int k  = idx % K;
    int j  = (idx / K) & 127;
    int q  = idx / (128*K);
    int u  = q*32 + (j >> 2), gt = j & 3;
    float v = (k < Kih) ? Wih[(gt*LH + u)*Kih + k] : Whh[(gt*LH + u)*LH + (k - Kih)];
    img[(size_t)q*128*KP + j*KP + k] = __float2bfloat16(v);
}

__global__ void k_prepb(const float* bi0, const float* bh0, const float* bi1, const float* bh1,
                        float* __restrict__ bc) {
    int idx = blockIdx.x*256 + threadIdx.x;
    if (idx >= 1024) return;
    int l = idx >> 9, r = idx & 511;
    int q = r >> 7, j = r & 127;
    int u = q*32 + (j >> 2), gt = j & 3;
    int w = gt*LH + u;
    bc[idx] = l ? (bi1[w] + bh1[w]) : (bi0[w] + bh0[w]);
}

// ---------------- fused LSTM step on mma.sync (bf16 HMMA) ----------------
// grid (NN/128, 4). CTA: D[128 rows x 128 gate-cols] = A[128,K] @ Wimg_q^T,
// then LSTM gate math + c/h update for its 32-unit quarter.
template<int KIH, bool FEAT, bool HAS_H>
__global__ void __launch_bounds__(256, 1)
k_step_mma(const float* __restrict__ a_scal,
           const float* __restrict__ gw, const float* __restrict__ gb,
           const __nv_bfloat16* __restrict__ ihA,
           const __nv_bfloat16* __restrict__ hprev,
           const __nv_bfloat16* __restrict__ Wimg,
           const float* __restrict__ biasC,
           float* __restrict__ c, __nv_bfloat16* __restrict__ hout, int NN)
{
    constexpr int KIMG = KIH + LH;              // image K extent
    constexpr int KP   = KIMG + 8;              // padded pitch (bf16)
    constexpr int K    = KIH + (HAS_H ? LH : 0);
    constexpr int NK16 = K / 16;

    extern __shared__ char smem[];
    char*  smA   = smem;
    char*  smB   = smem + 128*KP*2;
    float* smD   = (float*)(smem + 2*128*KP*2);     // [128][132]
    float* sbias = (float*)(smem + 2*128*KP*2 + 128*132*4);

    const uint32_t sA = smem_u32(smA);
    const uint32_t sB = smem_u32(smB);

    const int tid = threadIdx.x, wid = tid >> 5, lane = tid & 31;
    const int m0 = blockIdx.x*128, q = blockIdx.y;

    if (tid < 128) sbias[tid] = biasC[q*128 + tid];

    // ---- stage B: linear copy of this quarter's padded image (k < K only) ----
    {
        const __nv_bfloat16* imgq = Wimg + (size_t)q*128*KP;
        constexpr int CHR = K/8;                 // 16B chunks per row
        for (int idx = tid; idx < 128*CHR; idx += 256) {
            int row = idx / CHR, ch = idx - row*CHR;
            cp16(sB + (uint32_t)((row*KP + ch*8)*2), imgq + row*KP + ch*8);
        }
    }

    // ---- stage A ----
    if (FEAT) {
        // feat cols 0..KIH-1 = relu(a*gw+gb), built in-register (KIH = 64)
        for (int idx = tid; idx < 128*(KIH/8); idx += 256) {
            int row = idx >> 3, ch = idx & 7;
            float av = a_scal[m0 + row];
            uint32_t w[4];
#pragma unroll
            for (int i = 0; i < 4; i++) {
                int k = ch*8 + 2*i;
                float f0 = fmaxf(fmaf(av, gw[k],   gb[k]),   0.f);
                float f1 = fmaxf(fmaf(av, gw[k+1], gb[k+1]), 0.f);
                __nv_bfloat162 b2 = __floats2bfloat162_rn(f0, f1);
                w[i] = *reinterpret_cast<uint32_t*>(&b2);
            }
            *(uint4*)(smA + (row*KP + ch*8)*2) = make_uint4(w[0], w[1], w[2], w[3]);
        }
    } else {
        for (int idx = tid; idx < 128*(KIH/8); idx += 256) {
            int row = idx / (KIH/8), ch = idx % (KIH/8);
            cp16(sA + (uint32_t)((row*KP + ch*8)*2), ihA + (size_t)(m0+row)*LH + ch*8);
        }
    }
    if (HAS_H) {
        for (int idx = tid; idx < 128*16; idx += 256) {
            int row = idx >> 4, ch = idx & 15;
            cp16(sA + (uint32_t)((row*KP + KIH + ch*8)*2), hprev + (size_t)(m0+row)*LH + ch*8);
        }
    }

    asm volatile("cp.async.commit_group;");
    asm volatile("cp.async.wait_group 0;");
    __syncthreads();

    // ---- mma.sync K-loop: warp (wm 0..3, wn 0..1), warp tile 32 x 64 ----
    const int wm = wid >> 1, wn = wid & 1;
    const int lr = lane & 7, g = lane >> 3;
    const uint32_t aAddr = sA + (uint32_t)(((wm*32 + (g & 1)*8 + lr)*KP + (g >> 1)*8) * 2);
    const uint32_t bAddr = sB + (uint32_t)(((wn*64 + (g >> 1)*8 + lr)*KP + (g & 1)*8) * 2);

    float acc[2][8][4];
#pragma unroll
    for (int mt = 0; mt < 2; mt++)
#pragma unroll
        for (int nt = 0; nt < 8; nt++)
#pragma unroll
            for (int i = 0; i < 4; i++) acc[mt][nt][i] = 0.f;

#pragma unroll
    for (int s = 0; s < NK16; s++) {
        uint32_t a0[4], a1[4], bB[4][4];
        ldsm4(aAddr + s*32,             a0[0], a0[1], a0[2], a0[3]);
        ldsm4(aAddr + 16*KP*2 + s*32,   a1[0], a1[1], a1[2], a1[3]);
#pragma unroll
        for (int p = 0; p < 4; p++)
            ldsm4(bAddr + p*16*KP*2 + s*32, bB[p][0], bB[p][1], bB[p][2], bB[p][3]);
#pragma unroll
        for (int p = 0; p < 4; p++) {
            mma16816(acc[0][2*p],   a0, &bB[p][0]);
            mma16816(acc[0][2*p+1], a0, &bB[p][2]);
            mma16816(acc[1][2*p],   a1, &bB[p][0]);
            mma16816(acc[1][2*p+1], a1, &bB[p][2]);
        }
    }

    // ---- dump accumulators to smem D [row][j], pitch 132 ----
#pragma unroll
    for (int mt = 0; mt < 2; mt++) {
        int r0 = wm*32 + mt*16 + (lane >> 2);
#pragma unroll
        for (int nt = 0; nt < 8; nt++) {
            int j = wn*64 + nt*8 + 2*(lane & 3);
            *(float2*)(smD + r0*132 + j)       = make_float2(acc[mt][nt][0], acc[mt][nt][1]);
            *(float2*)(smD + (r0 + 8)*132 + j) = make_float2(acc[mt][nt][2], acc[mt][nt][3]);
        }
    }
    __syncthreads();

    // ---- epilogue: coalesced gate math + c/h update ----
#pragma unroll
    for (int it = 0; it < 16; it++) {
        int idx = tid + it*256;
        int row = idx >> 5, ul = idx & 31;
        float4 g4 = *(float4*)(smD + row*132 + 4*ul);     // i, f, g, o
        int m = m0 + row, u = q*32 + ul;
        float gi = g4.x + sbias[4*ul + 0];
        float gf = g4.y + sbias[4*ul + 1];
        float gg = g4.z + sbias[4*ul + 2];
        float go = g4.w + sbias[4*ul + 3];
        float cn;
        if (HAS_H) cn = sigmfast(gf)*c[(size_t)m*LH + u] + sigmfast(gi)*tanhfast(gg);
        else       cn = sigmfast(gi)*tanhfast(gg);
        c[(size_t)m*LH + u] = cn;
        hout[(size_t)m*LH + u] = __float2bfloat16(sigmfast(go)*tanhfast(cn));
    }
}

// ---------------- head: out = x_t + relu(h@pw1^T+pb1)@pw2^T + pb2 ----------------
__global__ void k_head(const __nv_bfloat16* __restrict__ h, const float* __restrict__ x,
                       const float* __restrict__ pw1, const float* __restrict__ pb1,
                       const float* __restrict__ pw2, const float* __restrict__ pb2,
                       float* __restrict__ out, int NN) {
    __shared__ float w1s[128][65];
    __shared__ float w2s[64], b1s[64];
    const int tid = threadIdx.x;
    for (int idx = tid; idx < 64*128; idx += 256) {
        int j = idx >> 7, k = idx & 127;
        w1s[k][j] = pw1[idx];
    }
    if (tid < 64) { w2s[tid] = pw2[tid]; b1s[tid] = pb1[tid]; }
    __syncthreads();

    int warp = tid >> 5, lane = tid & 31;
    int n = blockIdx.x*8 + warp;
    if (n >= NN) return;
    const __nv_bfloat16* hr = h + (size_t)n*LH;
    float s0 = b1s[lane], s1 = b1s[lane+32];
#pragma unroll 8
    for (int k = 0; k < 128; k++) {
        float hv = __bfloat162float(hr[k]);
        s0 = fmaf(hv, w1s[k][lane],    s0);
        s1 = fmaf(hv, w1s[k][lane+32], s1);
    }
    float part = fmaxf(s0, 0.f)*w2s[lane] + fmaxf(s1, 0.f)*w2s[lane+32];
#pragma unroll
    for (int o = 16; o; o >>= 1) part += __shfl_xor_sync(0xffffffffu, part, o);
    if (lane == 0) out[n] = part + pb2[0] + x[n*T_STEPS + (T_STEPS-1)];
}

// ---------------- launcher ----------------
extern "C" void kernel_launch(void* const* d_in, const int* in_sizes, int n_in,
                              void* d_out, int out_size) {
    const float* x    = (const float*)d_in[0];
    const int*   ei   = (const int*)  d_in[1];
    const float* gw   = (const float*)d_in[2];
    const float* gb   = (const float*)d_in[3];
    const float* wih0 = (const float*)d_in[4];
    const float* whh0 = (const float*)d_in[5];
    const float* bih0 = (const float*)d_in[6];
    const float* bhh0 = (const float*)d_in[7];
    const float* wih1 = (const float*)d_in[8];
    const float* whh1 = (const float*)d_in[9];
    const float* bih1 = (const float*)d_in[10];
    const float* bhh1 = (const float*)d_in[11];
    const float* pw1  = (const float*)d_in[12];
    const float* pb1  = (const float*)d_in[13];
    const float* pw2  = (const float*)d_in[14];
    const float* pb2  = (const float*)d_in[15];
    float* out = (float*)d_out;

    const int NN = in_sizes[0] / T_STEPS;   // 16000
    const int E  = in_sizes[1] / 2;         // 256000
    const int* src = ei;
    const int* dst = ei + E;

    float *p_deg, *p_dinv, *p_acc, *p_a, *p_c, *p_biasC;
    __nv_bfloat16 *p_y0b, *p_hAb, *p_hBb, *p_img0, *p_img1;
    cudaGetSymbolAddress((void**)&p_deg,   d_deg);
    cudaGetSymbolAddress((void**)&p_dinv,  d_dinv);
    cudaGetSymbolAddress((void**)&p_acc,   d_acc);
    cudaGetSymbolAddress((void**)&p_a,     d_a);
    cudaGetSymbolAddress((void**)&p_c,     d_c);
    cudaGetSymbolAddress((void**)&p_biasC, d_biasC);
    cudaGetSymbolAddress((void**)&p_y0b,   d_y0b);
    cudaGetSymbolAddress((void**)&p_hAb,   d_hAb);
    cudaGetSymbolAddress((void**)&p_hBb,   d_hBb);
    cudaGetSymbolAddress((void**)&p_img0,  d_img0);
    cudaGetSymbolAddress((void**)&p_img1,  d_img1);

    // dynamic smem: 2 * 128*KP*2 (A,B) + 128*132*4 (D) + 512 (bias)
    const int SMB0 = 2*128*200*2 + 128*132*4 + 512;   // 170496  (KIMG=192)
    const int SMB1 = 2*128*264*2 + 128*132*4 + 512;   // 203264  (KIMG=256)
    cudaFuncSetAttribute(k_step_mma<64,  true,  false>, cudaFuncAttributeMaxDynamicSharedMemorySize, SMB0);
    cudaFuncSetAttribute(k_step_mma<64,  true,  true >, cudaFuncAttributeMaxDynamicSharedMemorySize, SMB0);
    cudaFuncSetAttribute(k_step_mma<128, false, false>, cudaFuncAttributeMaxDynamicSharedMemorySize, SMB1);
    cudaFuncSetAttribute(k_step_mma<128, false, true >, cudaFuncAttributeMaxDynamicSharedMemorySize, SMB1);

    // weight/bias images
    k_prepw_mma<<<(4*128*192 + 255)/256, 256>>>(wih0, whh0, p_img0, HID, 200);
    k_prepw_mma<<<(4*128*256 + 255)/256, 256>>>(wih1, whh1, p_img1, LH,  264);
    k_prepb<<<4, 256>>>(bih0, bhh0, bih1, bhh1, p_biasC);

    // GCN scalar aggregation -> d_a [t][n]
    k_deg_init    <<<(NN + 255)/256, 256>>>(p_deg, NN);
    k_deg_edges   <<<(E  + 255)/256, 256>>>(dst, p_deg, E);
    k_dinv_accinit<<<(NN + 255)/256, 256>>>(x, p_deg, p_dinv, p_acc, NN);
    k_scatter     <<<(E  + 255)/256, 256>>>(src, dst, x, p_dinv, p_acc, E);
    k_afin        <<<(NN*T_STEPS + 255)/256, 256>>>(p_acc, p_dinv, p_a, NN);

    dim3 gS(NN/128, 4);

    // Layer 0 (K = 64 feat [+128 h])
    k_step_mma<64, true, false><<<gS, 256, SMB0>>>(
        p_a, gw, gb, nullptr, nullptr, p_img0, p_biasC, p_c, p_y0b, NN);
    for (int t = 1; t < T_STEPS; t++)
        k_step_mma<64, true, true><<<gS, 256, SMB0>>>(
            p_a + (size_t)t*NN, gw, gb, nullptr, p_y0b + (size_t)(t-1)*NN*LH,
            p_img0, p_biasC, p_c, p_y0b + (size_t)t*NN*LH, NN);

    // Layer 1 (K = 128 ih [+128 h])
    k_step_mma<128, false, false><<<gS, 256, SMB1>>>(
        nullptr, nullptr, nullptr, p_y0b, nullptr, p_img1, p_biasC + 512, p_c, p_hAb, NN);
    __nv_bfloat16* hin = p_hAb; __nv_bfloat16* hout = p_hBb;
    for (int t = 1; t < T_STEPS; t++) {
        k_step_mma<128, false, true><<<gS, 256, SMB1>>>(
            nullptr, nullptr, nullptr, p_y0b + (size_t)t*NN*LH, hin,
            p_img1, p_biasC + 512, p_c, hout, NN);
        __nv_bfloat16* tmp = hin; hin = hout; hout = tmp;
    }

    // Head + residual
    k_head<<<(NN + 7)/8, 256>>>(hin, x, pw1, pb1, pw2, pb2, out, NN);
}

// round 7
// speedup vs baseline: 3.5581x; 1.0672x over previous
#include <cuda_runtime.h>
#include <cuda_bf16.h>
#include <math.h>
#include <stdint.h>

#define T_STEPS 5
#define HID 64
#define LH 128
#define NNV 16000
#define MBTOT 125        // 16000 / 128 m-blocks

// ---------------- scratch (device globals; no runtime allocation) ----------------
__device__ float d_deg [NNV];
__device__ float d_dinv[NNV];
__device__ float d_acc [NNV*T_STEPS];
__device__ float d_c   [(size_t)NNV*LH];
__device__ __nv_bfloat16 d_y0b [(size_t)T_STEPS*NNV*LH];
__device__ __nv_bfloat16 d_hAb [(size_t)NNV*LH];
__device__ __nv_bfloat16 d_hBb [(size_t)NNV*LH];
__device__ __nv_bfloat16 d_img0[4*128*200];   // layer0 weight image [q][j][k], pitch 200
__device__ __nv_bfloat16 d_img1[4*128*264];   // layer1, pitch 264
__device__ float d_biasC[1024];               // [layer][q][j]
__device__ unsigned d_barc = 0;               // grid barrier count
__device__ unsigned d_barg = 0;               // grid barrier generation (monotonic, replay-safe)

// ---------------- helpers ----------------
__device__ __forceinline__ float tanhfast(float x) {
    float y; asm("tanh.approx.f32 %0, %1;" : "=f"(y) : "f"(x)); return y;
}
__device__ __forceinline__ float sigmfast(float x) { return fmaf(tanhfast(0.5f*x), 0.5f, 0.5f); }

__device__ __forceinline__ uint32_t smem_u32(const void* p) {
    uint32_t a;
    asm("{ .reg .u64 t; cvta.to.shared.u64 t, %1; cvt.u32.u64 %0, t; }" : "=r"(a) : "l"(p));
    return a;
}
__device__ __forceinline__ void cp16(uint32_t d, const void* s) {
    asm volatile("cp.async.cg.shared.global [%0], [%1], 16;" :: "r"(d), "l"(s));
}
__device__ __forceinline__ void sts128(uint32_t a, uint4 v) {
    asm volatile("st.shared.v4.b32 [%0], {%1,%2,%3,%4};" :: "r"(a), "r"(v.x), "r"(v.y), "r"(v.z), "r"(v.w) : "memory");
}
__device__ __forceinline__ void ldsm4(uint32_t a, uint32_t& r0, uint32_t& r1, uint32_t& r2, uint32_t& r3) {
    asm volatile("ldmatrix.sync.aligned.m8n8.x4.shared.b16 {%0,%1,%2,%3}, [%4];"
                 : "=r"(r0), "=r"(r1), "=r"(r2), "=r"(r3) : "r"(a));
}
__device__ __forceinline__ void mma16816(float* d, const uint32_t* a, const uint32_t* b) {
    asm volatile("mma.sync.aligned.m16n8k16.row.col.f32.bf16.bf16.f32 "
        "{%0,%1,%2,%3}, {%4,%5,%6,%7}, {%8,%9}, {%0,%1,%2,%3};"
        : "+f"(d[0]), "+f"(d[1]), "+f"(d[2]), "+f"(d[3])
        : "r"(a[0]), "r"(a[1]), "r"(a[2]), "r"(a[3]), "r"(b[0]), "r"(b[1]));
}

__device__ __forceinline__ void gridbar(int nb) {
    __syncthreads();
    __threadfence();
    if (threadIdx.x == 0) {
        volatile unsigned* vg = &d_barg;
        unsigned gen = *vg;
        unsigned t = atomicAdd(&d_barc, 1u);
        if (t == (unsigned)(nb - 1)) {
            atomicExch(&d_barc, 0u);
            __threadfence();
            atomicExch(&d_barg, gen + 1u);
        } else {
            while (*vg == gen) __nanosleep(64);
        }
    }
    __syncthreads();
}

// smem layout (bytes)
#define SB_B    0
#define SB_A0   67584
#define SB_A1   135168
#define SB_BIAS 202752
#define SB_GWGB 203264
#define SMB_TOT 203776

// ---------------- GCN scalar pipeline ----------------
__global__ void k_deg_init(float* deg, int n) {
    int i = blockIdx.x*blockDim.x + threadIdx.x;
    if (i < n) deg[i] = 1.0f;
}
__global__ void k_deg_edges(const int* __restrict__ dst, float* deg, int E) {
    int e = blockIdx.x*blockDim.x + threadIdx.x;
    if (e < E) atomicAdd(&deg[dst[e]], 1.0f);
}
__global__ void k_dinv_accinit(const float* __restrict__ x, const float* __restrict__ deg,
                               float* __restrict__ dinv, float* __restrict__ acc, int n) {
    int i = blockIdx.x*blockDim.x + threadIdx.x;
    if (i >= n) return;
    float di = rsqrtf(deg[i]);
    dinv[i] = di;
#pragma unroll
    for (int t = 0; t < T_STEPS; t++)
        acc[i*T_STEPS + t] = x[i*T_STEPS + t] * di;
}
__global__ void k_scatter(const int* __restrict__ src, const int* __restrict__ dst,
                          const float* __restrict__ x, const float* __restrict__ dinv,
                          float* __restrict__ acc, int E) {
    int e = blockIdx.x*blockDim.x + threadIdx.x;
    if (e >= E) return;
    int s = src[e], d = dst[e];
    float ds = dinv[s];
#pragma unroll
    for (int t = 0; t < T_STEPS; t++)
        atomicAdd(&acc[d*T_STEPS + t], x[s*T_STEPS + t] * ds);
}

// ---------------- weight/bias pre-transform ----------------
__global__ void k_prepw_mma(const float* __restrict__ Wih, const float* __restrict__ Whh,
                            __nv_bfloat16* __restrict__ img, int Kih, int KP) {
    int K = Kih + LH;
    int idx = blockIdx.x*256 + threadIdx.x;
    if (idx >= 4*128*K) return;
    int k  = idx % K;
    int j  = (idx / K) & 127;
    int q  = idx / (128*K);
    int u  = q*32 + (j >> 2), gt = j & 3;
    float v = (k < Kih) ? Wih[(gt*LH + u)*Kih + k] : Whh[(gt*LH + u)*LH + (k - Kih)];
    img[(size_t)q*128*KP + j*KP + k] = __float2bfloat16(v);
}
__global__ void k_prepb(const float* bi0, const float* bh0, const float* bi1, const float* bh1,
                        float* __restrict__ bc) {
    int idx = blockIdx.x*256 + threadIdx.x;
    if (idx >= 1024) return;
    int l = idx >> 9, r = idx & 511;
    int q = r >> 7, j = r & 127;
    int u = q*32 + (j >> 2), gt = j & 3;
    int w = gt*LH + u;
    bc[idx] = l ? (bi1[w] + bh1[w]) : (bi0[w] + bh0[w]);
}

// ---------------- persistent 2-layer LSTM (all 10 steps, grid barriers) ----------------
__global__ void __launch_bounds__(256, 1)
k_steps(const float* __restrict__ gw, const float* __restrict__ gb, int NB)
{
    extern __shared__ char smem[];
    const uint32_t sb = smem_u32(smem);
    float* sbias = (float*)(smem + SB_BIAS);
    float* sgwgb = (float*)(smem + SB_GWGB);

    const int tid = threadIdx.x, wid = tid >> 5, lane = tid & 31;
    const int q = blockIdx.x & 3, slot = blockIdx.x >> 2, nsl = NB >> 2;
    const int wm = wid >> 1, wn = wid & 1, lr = lane & 7, g = lane >> 3;

    if (tid < 128) sgwgb[tid] = (tid < 64) ? gw[tid] : gb[tid - 64];
    __syncthreads();

    for (int layer = 0; layer < 2; layer++) {
        const int KIH = layer ? 128 : 64;
        const int KP  = layer ? 264 : 200;
        const __nv_bfloat16* img = layer ? d_img1 : d_img0;

        // stage this quarter's B image (resident for the whole layer)
        {
            int nch = (128*KP*2)/16;
            const char* src = (const char*)(img + (size_t)q*128*KP);
            for (int i = tid; i < nch; i += 256) cp16(sb + SB_B + i*16, src + i*16);
        }
        if (tid < 128) sbias[tid] = d_biasC[layer*512 + q*128 + tid];
        asm volatile("cp.async.commit_group;");

        for (int t = 0; t < T_STEPS; t++) {
            const __nv_bfloat16* ihsrc = layer ? (d_y0b + (size_t)t*NNV*LH) : nullptr;
            const __nv_bfloat16* hprev;
            __nv_bfloat16* hout;
            if (layer == 0) {
                hprev = t ? d_y0b + (size_t)(t-1)*NNV*LH : nullptr;
                hout  = d_y0b + (size_t)t*NNV*LH;
            } else {
                hprev = t ? ((t & 1) ? d_hAb : d_hBb) : nullptr;
                hout  = (t & 1) ? d_hBb : d_hAb;           // t=4 -> d_hAb (head reads hA)
            }
            const int hasH = (t > 0);
            const int nk16 = (KIH + (hasH ? LH : 0)) >> 4;
            int buf = 0;

            auto stageA = [&](int mb, int bi) {
                uint32_t ab = sb + (bi ? SB_A1 : SB_A0);
                int m0s = mb*128;
                if (layer == 0) {
#pragma unroll
                    for (int it = 0; it < 4; it++) {           // feat cols 0..63
                        int idx = tid + it*256;
                        int row = idx >> 3, ch = idx & 7;
                        int m = m0s + row;
                        float av = d_acc[m*T_STEPS + t] * d_dinv[m];
                        uint32_t w[4];
#pragma unroll
                        for (int i = 0; i < 4; i++) {
                            int k = ch*8 + 2*i;
                            float f0 = fmaxf(fmaf(av, sgwgb[k],   sgwgb[64+k]),   0.f);
                            float f1 = fmaxf(fmaf(av, sgwgb[k+1], sgwgb[64+k+1]), 0.f);
                            __nv_bfloat162 b2 = __floats2bfloat162_rn(f0, f1);
                            w[i] = *reinterpret_cast<uint32_t*>(&b2);
                        }
                        sts128(ab + (uint32_t)((row*KP + ch*8)*2), make_uint4(w[0], w[1], w[2], w[3]));
                    }
                    if (hasH) {
#pragma unroll
                        for (int it = 0; it < 8; it++) {       // h cols 64..191
                            int idx = tid + it*256;
                            int row = idx >> 4, ch = idx & 15;
                            cp16(ab + (uint32_t)((row*KP + 64 + ch*8)*2),
                                 hprev + (size_t)(m0s + row)*LH + ch*8);
                        }
                    }
                } else {
#pragma unroll
                    for (int it = 0; it < 8; it++) {           // ih cols 0..127
                        int idx = tid + it*256;
                        int row = idx >> 4, ch = idx & 15;
                        cp16(ab + (uint32_t)((row*KP + ch*8)*2),
                             ihsrc + (size_t)(m0s + row)*LH + ch*8);
                    }
                    if (hasH) {
#pragma unroll
                        for (int it = 0; it < 8; it++) {       // h cols 128..255
                            int idx = tid + it*256;
                            int row = idx >> 4, ch = idx & 15;
                            cp16(ab + (uint32_t)((row*KP + 128 + ch*8)*2),
                                 hprev + (size_t)(m0s + row)*LH + ch*8);
                        }
                    }
                }
                asm volatile("cp.async.commit_group;");
            };

            stageA(slot, 0);

            for (int mb = slot; mb < MBTOT; mb += nsl) {
                asm volatile("cp.async.wait_group 0;");
                __syncthreads();

                uint32_t aBb = sb + (buf ? SB_A1 : SB_A0);
                uint32_t aAddr = aBb + (uint32_t)(((wm*32 + (g & 1)*8 + lr)*KP + (g >> 1)*8)*2);
                uint32_t bAddr = sb + SB_B + (uint32_t)(((wn*64 + (g >> 1)*8 + lr)*KP + (g & 1)*8)*2);

                float acc[2][8][4];
#pragma unroll
                for (int mt = 0; mt < 2; mt++)
#pragma unroll
                    for (int nt = 0; nt < 8; nt++)
#pragma unroll
                        for (int i = 0; i < 4; i++) acc[mt][nt][i] = 0.f;

#pragma unroll 4
                for (int s = 0; s < nk16; s++) {
                    uint32_t a0[4], a1[4], bB[4][4];
                    ldsm4(aAddr + s*32,                        a0[0], a0[1], a0[2], a0[3]);
                    ldsm4(aAddr + (uint32_t)(16*KP*2) + s*32,  a1[0], a1[1], a1[2], a1[3]);
#pragma unroll
                    for (int p = 0; p < 4; p++)
                        ldsm4(bAddr + (uint32_t)(p*16*KP*2) + s*32, bB[p][0], bB[p][1], bB[p][2], bB[p][3]);
#pragma unroll
                    for (int p = 0; p < 4; p++) {
                        mma16816(acc[0][2*p],   a0, &bB[p][0]);
                        mma16816(acc[0][2*p+1], a0, &bB[p][2]);
                        mma16816(acc[1][2*p],   a1, &bB[p][0]);
                        mma16816(acc[1][2*p+1], a1, &bB[p][2]);
                    }
                }
                __syncthreads();                 // everyone done reading A[buf]

                if (mb + nsl < MBTOT) stageA(mb + nsl, buf ^ 1);   // prefetch next A

                // D aliased over the dead A[buf]; two 64-col halves (wn==hf owns the half)
                float* smD = (float*)(smem + (buf ? SB_A1 : SB_A0));
                int m0s = mb*128;
#pragma unroll
                for (int hf = 0; hf < 2; hf++) {
                    if (wn == hf) {
#pragma unroll
                        for (int mt = 0; mt < 2; mt++) {
                            int r0 = wm*32 + mt*16 + (lane >> 2);
#pragma unroll
                            for (int nt = 0; nt < 8; nt++) {
                                int jl = nt*8 + 2*(lane & 3);
                                *(float2*)(smD + r0*68 + jl)       = make_float2(acc[mt][nt][0], acc[mt][nt][1]);
                                *(float2*)(smD + (r0 + 8)*68 + jl) = make_float2(acc[mt][nt][2], acc[mt][nt][3]);
                            }
                        }
                    }
                    __syncthreads();
#pragma unroll
                    for (int it = 0; it < 8; it++) {
                        int idx = tid + it*256;           // 128 rows x 16 units
                        int row = idx >> 4, ul = idx & 15;
                        float4 g4 = *(float4*)(smD + row*68 + 4*ul);
                        int m = m0s + row, u = q*32 + hf*16 + ul;
                        float gi = g4.x + sbias[hf*64 + 4*ul + 0];
                        float gf = g4.y + sbias[hf*64 + 4*ul + 1];
                        float gg = g4.z + sbias[hf*64 + 4*ul + 2];
                        float go = g4.w + sbias[hf*64 + 4*ul + 3];
                        float cn = hasH ? sigmfast(gf)*d_c[(size_t)m*LH + u] + sigmfast(gi)*tanhfast(gg)
                                        : sigmfast(gi)*tanhfast(gg);
                        d_c[(size_t)m*LH + u] = cn;
                        hout[(size_t)m*LH + u] = __float2bfloat16(sigmfast(go)*tanhfast(cn));
                    }
                    __syncthreads();
                }
                buf ^= 1;
            }
            gridbar(NB);
        }
    }
}

// ---------------- head: out = x_t + relu(h@pw1^T+pb1)@pw2^T + pb2 ----------------
__global__ void k_head(const __nv_bfloat16* __restrict__ h, const float* __restrict__ x,
                       const float* __restrict__ pw1, const float* __restrict__ pb1,
                       const float* __restrict__ pw2, const float* __restrict__ pb2,
                       float* __restrict__ out, int NN) {
    __shared__ float w1s[128][65];
    __shared__ float w2s[64], b1s[64];
    const int tid = threadIdx.x;
    for (int idx = tid; idx < 64*128; idx += 256) {
        int j = idx >> 7, k = idx & 127;
        w1s[k][j] = pw1[idx];
    }
    if (tid < 64) { w2s[tid] = pw2[tid]; b1s[tid] = pb1[tid]; }
    __syncthreads();

    int warp = tid >> 5, lane = tid & 31;
    int n = blockIdx.x*8 + warp;
    if (n >= NN) return;
    const __nv_bfloat16* hr = h + (size_t)n*LH;
    float s0 = b1s[lane], s1 = b1s[lane+32];
#pragma unroll 8
    for (int k = 0; k < 128; k++) {
        float hv = __bfloat162float(hr[k]);
        s0 = fmaf(hv, w1s[k][lane],    s0);
        s1 = fmaf(hv, w1s[k][lane+32], s1);
    }
    float part = fmaxf(s0, 0.f)*w2s[lane] + fmaxf(s1, 0.f)*w2s[lane+32];
#pragma unroll
    for (int o = 16; o; o >>= 1) part += __shfl_xor_sync(0xffffffffu, part, o);
    if (lane == 0) out[n] = part + pb2[0] + x[n*T_STEPS + (T_STEPS-1)];
}

// ---------------- launcher ----------------
extern "C" void kernel_launch(void* const* d_in, const int* in_sizes, int n_in,
                              void* d_out, int out_size) {
    const float* x    = (const float*)d_in[0];
    const int*   ei   = (const int*)  d_in[1];
    const float* gw   = (const float*)d_in[2];
    const float* gb   = (const float*)d_in[3];
    const float* wih0 = (const float*)d_in[4];
    const float* whh0 = (const float*)d_in[5];
    const float* bih0 = (const float*)d_in[6];
    const float* bhh0 = (const float*)d_in[7];
    const float* wih1 = (const float*)d_in[8];
    const float* whh1 = (const float*)d_in[9];
    const float* bih1 = (const float*)d_in[10];
    const float* bhh1 = (const float*)d_in[11];
    const float* pw1  = (const float*)d_in[12];
    const float* pb1  = (const float*)d_in[13];
    const float* pw2  = (const float*)d_in[14];
    const float* pb2  = (const float*)d_in[15];
    float* out = (float*)d_out;

    const int NN = in_sizes[0] / T_STEPS;   // 16000
    const int E  = in_sizes[1] / 2;         // 256000
    const int* src = ei;
    const int* dst = ei + E;

    float *p_deg, *p_dinv, *p_acc, *p_biasC;
    __nv_bfloat16 *p_hAb, *p_img0, *p_img1;
    cudaGetSymbolAddress((void**)&p_deg,   d_deg);
    cudaGetSymbolAddress((void**)&p_dinv,  d_dinv);
    cudaGetSymbolAddress((void**)&p_acc,   d_acc);
    cudaGetSymbolAddress((void**)&p_biasC, d_biasC);
    cudaGetSymbolAddress((void**)&p_hAb,   d_hAb);
    cudaGetSymbolAddress((void**)&p_img0,  d_img0);
    cudaGetSymbolAddress((void**)&p_img1,  d_img1);

    cudaFuncSetAttribute(k_steps, cudaFuncAttributeMaxDynamicSharedMemorySize, SMB_TOT);

    // persistent grid size: all CTAs must be simultaneously resident
    int dev = 0, sms = 0, occ = 0;
    cudaGetDevice(&dev);
    cudaDeviceGetAttribute(&sms, cudaDevAttrMultiProcessorCount, dev);
    cudaOccupancyMaxActiveBlocksPerMultiprocessor(&occ, k_steps, 256, SMB_TOT);
    if (occ < 1) occ = 1;
    int NB = sms * occ;
    if (NB > 4*MBTOT) NB = 4*MBTOT;
    NB &= ~3;
    if (NB < 4) NB = 4;

    // weight/bias images
    k_prepw_mma<<<(4*128*192 + 255)/256, 256>>>(wih0, whh0, p_img0, HID, 200);
    k_prepw_mma<<<(4*128*256 + 255)/256, 256>>>(wih1, whh1, p_img1, LH,  264);
    k_prepb<<<4, 256>>>(bih0, bhh0, bih1, bhh1, p_biasC);

    // GCN scalar aggregation
    k_deg_init    <<<(NN + 255)/256, 256>>>(p_deg, NN);
    k_deg_edges   <<<(E  + 255)/256, 256>>>(dst, p_deg, E);
    k_dinv_accinit<<<(NN + 255)/256, 256>>>(x, p_deg, p_dinv, p_acc, NN);
    k_scatter     <<<(E  + 255)/256, 256>>>(src, dst, x, p_dinv, p_acc, E);

    // both LSTM layers, all 10 steps, one persistent kernel
    k_steps<<<NB, 256, SMB_TOT>>>(gw, gb, NB);

    // head + residual (layer1 h[4] lives in d_hAb)
    k_head<<<(NN + 7)/8, 256>>>(p_hAb, x, pw1, pb1, pw2, pb2, out, NN);
}

// round 8
// speedup vs baseline: 3.6172x; 1.0166x over previous
#include <cuda_runtime.h>
#include <cuda_bf16.h>
#include <math.h>
#include <stdint.h>

#define T_STEPS 5
#define HID 64
#define LH 128
#define NNV 16000
#define MBTOT 125        // 16000 / 128 m-blocks

// ---------------- scratch (device globals; no runtime allocation) ----------------
__device__ float d_deg [NNV];
__device__ float d_dinv[NNV];
__device__ float d_acc [NNV*T_STEPS];
__device__ float d_c   [(size_t)NNV*LH];
__device__ __nv_bfloat16 d_y0b [(size_t)T_STEPS*NNV*LH];
__device__ __nv_bfloat16 d_hAb [(size_t)NNV*LH];
__device__ __nv_bfloat16 d_hBb [(size_t)NNV*LH];
__device__ __nv_bfloat16 d_img0[4*128*200];   // layer0 weight image [q][j][k], pitch 200
__device__ __nv_bfloat16 d_img1[4*128*264];   // layer1, pitch 264
__device__ float d_biasC[1024];               // [layer][q][j]
__device__ unsigned d_barc = 0;
__device__ unsigned d_barg = 0;               // generation (monotonic, replay-safe)

// ---------------- helpers ----------------
__device__ __forceinline__ float tanhfast(float x) {
    float y; asm("tanh.approx.f32 %0, %1;" : "=f"(y) : "f"(x)); return y;
}
__device__ __forceinline__ float sigmfast(float x) { return fmaf(tanhfast(0.5f*x), 0.5f, 0.5f); }

__device__ __forceinline__ uint32_t smem_u32(const void* p) {
    uint32_t a;
    asm("{ .reg .u64 t; cvta.to.shared.u64 t, %1; cvt.u32.u64 %0, t; }" : "=r"(a) : "l"(p));
    return a;
}
__device__ __forceinline__ void cp16(uint32_t d, const void* s) {
    asm volatile("cp.async.cg.shared.global [%0], [%1], 16;" :: "r"(d), "l"(s));
}
__device__ __forceinline__ void sts128(uint32_t a, uint4 v) {
    asm volatile("st.shared.v4.b32 [%0], {%1,%2,%3,%4};" :: "r"(a), "r"(v.x), "r"(v.y), "r"(v.z), "r"(v.w) : "memory");
}
__device__ __forceinline__ void ldsm4(uint32_t a, uint32_t& r0, uint32_t& r1, uint32_t& r2, uint32_t& r3) {
    asm volatile("ldmatrix.sync.aligned.m8n8.x4.shared.b16 {%0,%1,%2,%3}, [%4];"
                 : "=r"(r0), "=r"(r1), "=r"(r2), "=r"(r3) : "r"(a));
}
__device__ __forceinline__ void mma16816(float* d, const uint32_t* a, const uint32_t* b) {
    asm volatile("mma.sync.aligned.m16n8k16.row.col.f32.bf16.bf16.f32 "
        "{%0,%1,%2,%3}, {%4,%5,%6,%7}, {%8,%9}, {%0,%1,%2,%3};"
        : "+f"(d[0]), "+f"(d[1]), "+f"(d[2]), "+f"(d[3])
        : "r"(a[0]), "r"(a[1]), "r"(a[2]), "r"(a[3]), "r"(b[0]), "r"(b[1]));
}

__device__ __forceinline__ void gridbar(int nb) {
    __syncthreads();
    __threadfence();
    if (threadIdx.x == 0) {
        volatile unsigned* vg = &d_barg;
        unsigned gen = *vg;
        unsigned t = atomicAdd(&d_barc, 1u);
        if (t == (unsigned)(nb - 1)) {
            atomicExch(&d_barc, 0u);
            __threadfence();
            atomicExch(&d_barg, gen + 1u);
        } else {
            while (*vg == gen) __nanosleep(64);
        }
    }
    __syncthreads();
}

// smem layout (bytes)
#define SB_B    0
#define SB_A0   67584
#define SB_A1   135168
#define SB_BIAS 202752
#define SB_GWGB 203264
#define SMB_TOT 203776

// ---------------- A-tile staging (split: ih/feat part vs h part) ----------------
__device__ __forceinline__ void stage_ih(uint32_t ab, int layer, int t, int m0s,
                                         const float* sgwgb) {
    const int tid = threadIdx.x;
    if (layer == 0) {
        const int KP = 200;
#pragma unroll
        for (int it = 0; it < 4; it++) {             // feat cols 0..63 (built in-register)
            int idx = tid + it*256;
            int row = idx >> 3, ch = idx & 7;
            int m = m0s + row;
            float av = d_acc[m*T_STEPS + t] * d_dinv[m];
            uint32_t w[4];
#pragma unroll
            for (int i = 0; i < 4; i++) {
                int k = ch*8 + 2*i;
                float f0 = fmaxf(fmaf(av, sgwgb[k],   sgwgb[64+k]),   0.f);
                float f1 = fmaxf(fmaf(av, sgwgb[k+1], sgwgb[64+k+1]), 0.f);
                __nv_bfloat162 b2 = __floats2bfloat162_rn(f0, f1);
                w[i] = *reinterpret_cast<uint32_t*>(&b2);
            }
            sts128(ab + (uint32_t)((row*KP + ch*8)*2), make_uint4(w[0], w[1], w[2], w[3]));
        }
    } else {
        const int KP = 264;
        const __nv_bfloat16* ihsrc = d_y0b + (size_t)t*NNV*LH;
#pragma unroll
        for (int it = 0; it < 8; it++) {             // ih cols 0..127
            int idx = tid + it*256;
            int row = idx >> 4, ch = idx & 15;
            cp16(ab + (uint32_t)((row*KP + ch*8)*2), ihsrc + (size_t)(m0s + row)*LH + ch*8);
        }
    }
}

__device__ __forceinline__ void stage_h(uint32_t ab, int layer, int t, int m0s) {
    const int tid = threadIdx.x;
    const int KP  = layer ? 264 : 200;
    const int KIH = layer ? 128 : 64;
    const __nv_bfloat16* hprev = layer ? ((t & 1) ? d_hAb : d_hBb)
                                       : d_y0b + (size_t)(t-1)*NNV*LH;
#pragma unroll
    for (int it = 0; it < 8; it++) {
        int idx = tid + it*256;
        int row = idx >> 4, ch = idx & 15;
        cp16(ab + (uint32_t)((row*KP + KIH + ch*8)*2), hprev + (size_t)(m0s + row)*LH + ch*8);
    }
}

// ---------------- GCN scalar pipeline ----------------
__global__ void k_deg_edges(const int* __restrict__ dst, float* deg, int E) {
    int e = blockIdx.x*blockDim.x + threadIdx.x;
    if (e < E) atomicAdd(&deg[dst[e]], 1.0f);
}
__global__ void k_dinv_accinit(const float* __restrict__ x, const float* __restrict__ deg,
                               float* __restrict__ dinv, float* __restrict__ acc, int n) {
    int i = blockIdx.x*blockDim.x + threadIdx.x;
    if (i >= n) return;
    float di = rsqrtf(deg[i]);
    dinv[i] = di;
#pragma unroll
    for (int t = 0; t < T_STEPS; t++)
        acc[i*T_STEPS + t] = x[i*T_STEPS + t] * di;
}
__global__ void k_scatter(const int* __restrict__ src, const int* __restrict__ dst,
                          const float* __restrict__ x, const float* __restrict__ dinv,
                          float* __restrict__ acc, int E) {
    int e = blockIdx.x*blockDim.x + threadIdx.x;
    if (e >= E) return;
    int s = src[e], d = dst[e];
    float ds = dinv[s];
#pragma unroll
    for (int t = 0; t < T_STEPS; t++)
        atomicAdd(&acc[d*T_STEPS + t], x[s*T_STEPS + t] * ds);
}

// ---------------- weight/bias pre-transform (+ fused deg-init / bias prep) ----------------
__global__ void k_prepw_mma(const float* __restrict__ Wih, const float* __restrict__ Whh,
                            __nv_bfloat16* __restrict__ img, int Kih, int KP,
                            float* deg, int nn,
                            const float* bi, const float* bh, float* bc) {
    int gid = blockIdx.x*256 + threadIdx.x;
    if (deg && gid < nn) deg[gid] = 1.0f;
    if (bc && gid < 512) {
        int q = gid >> 7, j = gid & 127;
        int u = q*32 + (j >> 2), gt = j & 3;
        int w = gt*LH + u;
        bc[gid] = bi[w] + bh[w];
    }
    int K = Kih + LH;
    if (gid >= 4*128*K) return;
    int k  = gid % K;
    int j  = (gid / K) & 127;
    int q  = gid / (128*K);
    int u  = q*32 + (j >> 2), gt = j & 3;
    float v = (k < Kih) ? Wih[(gt*LH + u)*Kih + k] : Whh[(gt*LH + u)*LH + (k - Kih)];
    img[(size_t)q*128*KP + j*KP + k] = __float2bfloat16(v);
}

// ---------------- persistent 2-layer LSTM (10 phases, grid barriers) ----------------
__global__ void __launch_bounds__(256, 1)
k_steps(const float* __restrict__ gw, const float* __restrict__ gb, int NB)
{
    extern __shared__ char smem[];
    const uint32_t sb = smem_u32(smem);
    float* sbias = (float*)(smem + SB_BIAS);
    float* sgwgb = (float*)(smem + SB_GWGB);

    const int tid = threadIdx.x, wid = tid >> 5, lane = tid & 31;
    const int q = blockIdx.x & 3, slot = blockIdx.x >> 2, nsl = NB >> 2;
    const int wm = wid >> 1, wn = wid & 1, lr = lane & 7, g = lane >> 3;

    if (tid < 128) sgwgb[tid] = (tid < 64) ? gw[tid] : gb[tid - 64];
    __syncthreads();

    int prev_layer = -1;
    for (int ph = 0; ph < 10; ph++) {
        const int layer = ph / 5, t = ph - layer*5;
        const int KIH = layer ? 128 : 64;
        const int KP  = layer ? 264 : 200;
        const int hasH = (t > 0);
        const int nk16 = (KIH + (hasH ? LH : 0)) >> 4;
        __nv_bfloat16* hout = layer ? ((t & 1) ? d_hBb : d_hAb)      // t=4 -> d_hAb
                                    : d_y0b + (size_t)t*NNV*LH;

        if (layer != prev_layer) {       // stage this quarter's B image (resident per layer)
            prev_layer = layer;
            const __nv_bfloat16* img = layer ? d_img1 : d_img0;
            int nch = (128*KP*2)/16;
            const char* srcB = (const char*)(img + (size_t)q*128*KP);
            for (int i = tid; i < nch; i += 256) cp16(sb + SB_B + i*16, srcB + i*16);
            if (tid < 128) sbias[tid] = d_biasC[layer*512 + q*128 + tid];
        }
        if (ph == 0) stage_ih(sb + SB_A0, 0, 0, slot*128, sgwgb);   // otherwise pre-staged before barrier
        if (hasH)    stage_h(sb + SB_A0, layer, t, slot*128);
        asm volatile("cp.async.commit_group;");

        int buf = 0;
        for (int mb = slot; mb < MBTOT; mb += nsl) {
            asm volatile("cp.async.wait_group 0;");
            __syncthreads();

            uint32_t aBb = sb + (buf ? SB_A1 : SB_A0);
            uint32_t aAddr = aBb + (uint32_t)(((wm*32 + (g & 1)*8 + lr)*KP + (g >> 1)*8)*2);
            uint32_t bAddr = sb + SB_B + (uint32_t)(((wn*64 + (g >> 1)*8 + lr)*KP + (g & 1)*8)*2);

            float acc[2][8][4];
#pragma unroll
            for (int mt = 0; mt < 2; mt++)
#pragma unroll
                for (int nt = 0; nt < 8; nt++)
#pragma unroll
                    for (int i = 0; i < 4; i++) acc[mt][nt][i] = 0.f;

#pragma unroll 4
            for (int s = 0; s < nk16; s++) {
                uint32_t a0[4], a1[4], bB[4][4];
                ldsm4(aAddr + s*32,                        a0[0], a0[1], a0[2], a0[3]);
                ldsm4(aAddr + (uint32_t)(16*KP*2) + s*32,  a1[0], a1[1], a1[2], a1[3]);
#pragma unroll
                for (int p = 0; p < 4; p++)
                    ldsm4(bAddr + (uint32_t)(p*16*KP*2) + s*32, bB[p][0], bB[p][1], bB[p][2], bB[p][3]);
#pragma unroll
                for (int p = 0; p < 4; p++) {
                    mma16816(acc[0][2*p],   a0, &bB[p][0]);
                    mma16816(acc[0][2*p+1], a0, &bB[p][2]);
                    mma16816(acc[1][2*p],   a1, &bB[p][0]);
                    mma16816(acc[1][2*p+1], a1, &bB[p][2]);
                }
            }
            __syncthreads();                 // A[buf] now dead

            if (mb + nsl < MBTOT) {          // prefetch next A into other buffer
                uint32_t ab = sb + ((buf ^ 1) ? SB_A1 : SB_A0);
                stage_ih(ab, layer, t, (mb + nsl)*128, sgwgb);
                if (hasH) stage_h(ab, layer, t, (mb + nsl)*128);
                asm volatile("cp.async.commit_group;");
            }

            // single-pass D dump onto dead A[buf] (128 x 132 fp32 = 67584 B, exact fit)
            float* smD = (float*)(smem + (buf ? SB_A1 : SB_A0));
            int m0s = mb*128;
#pragma unroll
            for (int mt = 0; mt < 2; mt++) {
                int r0 = wm*32 + mt*16 + (lane >> 2);
#pragma unroll
                for (int nt = 0; nt < 8; nt++) {
                    int j = wn*64 + nt*8 + 2*(lane & 3);
                    *(float2*)(smD + r0*132 + j)       = make_float2(acc[mt][nt][0], acc[mt][nt][1]);
                    *(float2*)(smD + (r0 + 8)*132 + j) = make_float2(acc[mt][nt][2], acc[mt][nt][3]);
                }
            }
            __syncthreads();

            // epilogue: full 32-unit pass, coalesced global update
#pragma unroll
            for (int it = 0; it < 16; it++) {
                int idx = tid + it*256;              // 128 rows x 32 units
                int row = idx >> 5, ul = idx & 31;
                float4 g4 = *(float4*)(smD + row*132 + 4*ul);
                int m = m0s + row, u = q*32 + ul;
                float gi = g4.x + sbias[4*ul + 0];
                float gf = g4.y + sbias[4*ul + 1];
                float gg = g4.z + sbias[4*ul + 2];
                float go = g4.w + sbias[4*ul + 3];
                float cn = hasH ? sigmfast(gf)*d_c[(size_t)m*LH + u] + sigmfast(gi)*tanhfast(gg)
                                : sigmfast(gi)*tanhfast(gg);
                d_c[(size_t)m*LH + u] = cn;
                hout[(size_t)m*LH + u] = __float2bfloat16(sigmfast(go)*tanhfast(cn));
            }
            buf ^= 1;
        }

        // pre-barrier prefetch: next phase's ih/feat part never depends on this step's h
        __syncthreads();
        if (ph < 9) {
            int nl = (ph + 1) / 5, nt2 = (ph + 1) - nl*5;
            stage_ih(sb + SB_A0, nl, nt2, slot*128, sgwgb);
            asm volatile("cp.async.commit_group;");
        }
        gridbar(NB);
    }
}

// ---------------- head: out = x_t + relu(h@pw1^T+pb1)@pw2^T + pb2 ----------------
__global__ void k_head(const __nv_bfloat16* __restrict__ h, const float* __restrict__ x,
                       const float* __restrict__ pw1, const float* __restrict__ pb1,
                       const float* __restrict__ pw2, const float* __restrict__ pb2,
                       float* __restrict__ out, int NN) {
    __shared__ float w1s[128][65];
    __shared__ float w2s[64], b1s[64];
    const int tid = threadIdx.x;
    for (int idx = tid; idx < 64*128; idx += 256) {
        int j = idx >> 7, k = idx & 127;
        w1s[k][j] = pw1[idx];
    }
    if (tid < 64) { w2s[tid] = pw2[tid]; b1s[tid] = pb1[tid]; }
    __syncthreads();

    int warp = tid >> 5, lane = tid & 31;
    int n = blockIdx.x*8 + warp;
    if (n >= NN) return;
    const __nv_bfloat16* hr = h + (size_t)n*LH;
    float s0 = b1s[lane], s1 = b1s[lane+32];
#pragma unroll 8
    for (int k = 0; k < 128; k++) {
        float hv = __bfloat162float(hr[k]);
        s0 = fmaf(hv, w1s[k][lane],    s0);
        s1 = fmaf(hv, w1s[k][lane+32], s1);
    }
    float part = fmaxf(s0, 0.f)*w2s[lane] + fmaxf(s1, 0.f)*w2s[lane+32];
#pragma unroll
    for (int o = 16; o; o >>= 1) part += __shfl_xor_sync(0xffffffffu, part, o);
    if (lane == 0) out[n] = part + pb2[0] + x[n*T_STEPS + (T_STEPS-1)];
}

// ---------------- launcher ----------------
extern "C" void kernel_launch(void* const* d_in, const int* in_sizes, int n_in,
                              void* d_out, int out_size) {
    const float* x    = (const float*)d_in[0];
    const int*   ei   = (const int*)  d_in[1];
    const float* gw   = (const float*)d_in[2];
    const float* gb   = (const float*)d_in[3];
    const float* wih0 = (const float*)d_in[4];
    const float* whh0 = (const float*)d_in[5];
    const float* bih0 = (const float*)d_in[6];
    const float* bhh0 = (const float*)d_in[7];
    const float* wih1 = (const float*)d_in[8];
    const float* whh1 = (const float*)d_in[9];
    const float* bih1 = (const float*)d_in[10];
    const float* bhh1 = (const float*)d_in[11];
    const float* pw1  = (const float*)d_in[12];
    const float* pb1  = (const float*)d_in[13];
    const float* pw2  = (const float*)d_in[14];
    const float* pb2  = (const float*)d_in[15];
    float* out = (float*)d_out;

    const int NN = in_sizes[0] / T_STEPS;   // 16000
    const int E  = in_sizes[1] / 2;         // 256000
    const int* src = ei;
    const int* dst = ei + E;

    float *p_deg, *p_dinv, *p_acc, *p_biasC;
    __nv_bfloat16 *p_hAb, *p_img0, *p_img1;
    cudaGetSymbolAddress((void**)&p_deg,   d_deg);
    cudaGetSymbolAddress((void**)&p_dinv,  d_dinv);
    cudaGetSymbolAddress((void**)&p_acc,   d_acc);
    cudaGetSymbolAddress((void**)&p_biasC, d_biasC);
    cudaGetSymbolAddress((void**)&p_hAb,   d_hAb);
    cudaGetSymbolAddress((void**)&p_img0,  d_img0);
    cudaGetSymbolAddress((void**)&p_img1,  d_img1);

    cudaFuncSetAttribute(k_steps, cudaFuncAttributeMaxDynamicSharedMemorySize, SMB_TOT);

    // persistent grid size: all CTAs simultaneously resident
    int dev = 0, sms = 0, occ = 0;
    cudaGetDevice(&dev);
    cudaDeviceGetAttribute(&sms, cudaDevAttrMultiProcessorCount, dev);
    cudaOccupancyMaxActiveBlocksPerMultiprocessor(&occ, k_steps, 256, SMB_TOT);
    if (occ < 1) occ = 1;
    int NB = sms * occ;
    if (NB > 4*MBTOT) NB = 4*MBTOT;
    NB &= ~3;
    if (NB < 4) NB = 4;

    // weight images (+ fused deg-init and bias prep)
    k_prepw_mma<<<(4*128*192 + 255)/256, 256>>>(wih0, whh0, p_img0, HID, 200,
                                                p_deg, NN, bih0, bhh0, p_biasC);
    k_prepw_mma<<<(4*128*256 + 255)/256, 256>>>(wih1, whh1, p_img1, LH,  264,
                                                nullptr, 0, bih1, bhh1, p_biasC + 512);

    // GCN scalar aggregation
    k_deg_edges   <<<(E  + 255)/256, 256>>>(dst, p_deg, E);
    k_dinv_accinit<<<(NN + 255)/256, 256>>>(x, p_deg, p_dinv, p_acc, NN);
    k_scatter     <<<(E  + 255)/256, 256>>>(src, dst, x, p_dinv, p_acc, E);

    // both LSTM layers, all 10 steps, one persistent kernel
    k_steps<<<NB, 256, SMB_TOT>>>(gw, gb, NB);

    // head + residual (layer1 h[4] lives in d_hAb)
    k_head<<<(NN + 7)/8, 256>>>(p_hAb, x, pw1, pb1, pw2, pb2, out, NN);
}

// round 9
// speedup vs baseline: 5.0351x; 1.3920x over previous
#include <cuda_runtime.h>
#include <cuda_bf16.h>
#include <stdint.h>

#define T_STEPS 5
#define LH 128
#define NNV 16000
#define NCTA 125        // 16000/128

// ---------------- scratch (device globals; no runtime allocation) ----------------
__device__ float d_deg [NNV];
__device__ float d_dinv[NNV];
__device__ float d_acc [NNV*T_STEPS];
__device__ __nv_bfloat16 d_y0b [(size_t)T_STEPS*NNV*LH];   // layer-0 hidden sequence
__device__ __nv_bfloat16 d_hAb [(size_t)NNV*LH];           // final layer-1 h
__device__ __nv_bfloat16 d_img0[512*200];                  // layer0 weight image [j][k], pitch 200
__device__ __nv_bfloat16 d_img1[512*264];                  // layer1, pitch 264
__device__ float d_biasC[1024];                            // [layer][u*4+gate]

// ---------------- helpers ----------------
__device__ __forceinline__ float tanhfast(float x) {
    float y; asm("tanh.approx.f32 %0, %1;" : "=f"(y) : "f"(x)); return y;
}
__device__ __forceinline__ float sigmfast(float x) { return fmaf(tanhfast(0.5f*x), 0.5f, 0.5f); }

__device__ __forceinline__ uint32_t smem_u32(const void* p) {
    uint32_t a;
    asm("{ .reg .u64 t; cvta.to.shared.u64 t, %1; cvt.u32.u64 %0, t; }" : "=r"(a) : "l"(p));
    return a;
}
__device__ __forceinline__ void cp16(uint32_t d, const void* s) {
    asm volatile("cp.async.cg.shared.global [%0], [%1], 16;" :: "r"(d), "l"(s));
}
__device__ __forceinline__ void sts128(uint32_t a, uint4 v) {
    asm volatile("st.shared.v4.b32 [%0], {%1,%2,%3,%4};" :: "r"(a), "r"(v.x), "r"(v.y), "r"(v.z), "r"(v.w) : "memory");
}
__device__ __forceinline__ void ldsm4(uint32_t a, uint32_t& r0, uint32_t& r1, uint32_t& r2, uint32_t& r3) {
    asm volatile("ldmatrix.sync.aligned.m8n8.x4.shared.b16 {%0,%1,%2,%3}, [%4];"
                 : "=r"(r0), "=r"(r1), "=r"(r2), "=r"(r3) : "r"(a));
}
__device__ __forceinline__ void mma16816(float* d, const uint32_t* a, const uint32_t* b) {
    asm volatile("mma.sync.aligned.m16n8k16.row.col.f32.bf16.bf16.f32 "
        "{%0,%1,%2,%3}, {%4,%5,%6,%7}, {%8,%9}, {%0,%1,%2,%3};"
        : "+f"(d[0]), "+f"(d[1]), "+f"(d[2]), "+f"(d[3])
        : "r"(a[0]), "r"(a[1]), "r"(a[2]), "r"(a[3]), "r"(b[0]), "r"(b[1]));
}

// ---------------- GCN scalar pipeline (4-edge ILP) ----------------
__global__ void k_deg_edges(const int* __restrict__ dst, float* deg, int E) {
    int e0 = (blockIdx.x*blockDim.x + threadIdx.x)*4;
#pragma unroll
    for (int j = 0; j < 4; j++) {
        int e = e0 + j;
        if (e < E) atomicAdd(&deg[dst[e]], 1.0f);
    }
}
__global__ void k_dinv_accinit(const float* __restrict__ x, const float* __restrict__ deg,
                               float* __restrict__ dinv, float* __restrict__ acc, int n) {
    int i = blockIdx.x*blockDim.x + threadIdx.x;
    if (i >= n) return;
    float di = rsqrtf(deg[i]);
    dinv[i] = di;
#pragma unroll
    for (int t = 0; t < T_STEPS; t++)
        acc[i*T_STEPS + t] = x[i*T_STEPS + t] * di;
}
__global__ void k_scatter(const int* __restrict__ src, const int* __restrict__ dst,
                          const float* __restrict__ x, const float* __restrict__ dinv,
                          float* __restrict__ acc, int E) {
    int e0 = (blockIdx.x*blockDim.x + threadIdx.x)*4;
#pragma unroll
    for (int j = 0; j < 4; j++) {
        int e = e0 + j;
        if (e < E) {
            int s = src[e], d = dst[e];
            float ds = dinv[s];
#pragma unroll
            for (int t = 0; t < T_STEPS; t++)
                atomicAdd(&acc[d*T_STEPS + t], x[s*T_STEPS + t] * ds);
        }
    }
}

// ---------------- weight/bias pre-transform ----------------
// img[j][k], j = 4*unit + gate (W row = gate*128+unit), k = [ih | hh], pitch KP.
__global__ void k_prepw(const float* __restrict__ Wih, const float* __restrict__ Whh,
                        __nv_bfloat16* __restrict__ img, int Kih, int KP,
                        float* deg, int nn,
                        const float* bi, const float* bh, float* bc) {
    int gid = blockIdx.x*256 + threadIdx.x;
    if (deg && gid < nn) deg[gid] = 1.0f;
    if (gid < 512) {
        int u = gid >> 2, gt = gid & 3;
        bc[gid] = bi[gt*LH + u] + bh[gt*LH + u];
    }
    int K = Kih + LH;
    if (gid >= 512*K) return;
    int k = gid % K, j = gid / K;
    int u = j >> 2, gt = j & 3;
    float v = (k < Kih) ? Wih[(gt*LH + u)*Kih + k] : Whh[(gt*LH + u)*LH + (k - Kih)];
    img[j*KP + k] = __float2bfloat16(v);
}

// ---------------- per-CTA-independent LSTM layer (all 5 steps, no grid barrier) ----
// CTA owns 128 rows x all 512 gate cols. h lives in the A-tile h-columns
// (written in place by the epilogue), c lives in smem. B streamed in 64-col
// double-buffered chunks. A fragments register-resident per step.
template<int LAYER>
__global__ void __launch_bounds__(256, 1)
k_lstm(const float* __restrict__ gw, const float* __restrict__ gb)
{
    constexpr int KIH  = LAYER ? 128 : 64;
    constexpr int KP   = KIH + LH + 8;          // 264 / 200
    constexpr int NK16 = (KIH + LH) / 16;       // 16 / 12
    constexpr int AB   = 128*KP*2;
    constexpr int CB   = 128*129*4;
    constexpr int BCH  = 64*KP*2;
    constexpr int OFF_C    = AB;
    constexpr int OFF_B    = AB + CB;
    constexpr int OFF_BIAS = OFF_B + 2*BCH;
    constexpr int OFF_GW   = OFF_BIAS + 2048;

    extern __shared__ char smem[];
    const uint32_t sb = smem_u32(smem);
    float* cS    = (float*)(smem + OFF_C);      // [128][129]
    float* sbias = (float*)(smem + OFF_BIAS);   // 512
    float* sgw   = (float*)(smem + OFF_GW);     // 64 gw + 64 gb

    const int tid = threadIdx.x, wid = tid >> 5, lane = tid & 31;
    const int g = lane >> 3, lr = lane & 7;
    const int m0s = blockIdx.x*128;
    const __nv_bfloat16* img = LAYER ? d_img1 : d_img0;

    if (LAYER == 0 && tid < 128) sgw[tid] = (tid < 64) ? gw[tid] : gb[tid - 64];
    for (int i = tid; i < 512; i += 256) sbias[i] = d_biasC[LAYER*512 + i];
    // zero A tile (h cols = h0 = 0) and c
    for (int i = tid; i < AB/16; i += 256) ((uint4*)smem)[i] = make_uint4(0,0,0,0);
    for (int i = tid; i < CB/16; i += 256) ((uint4*)(smem + OFF_C))[i] = make_uint4(0,0,0,0);
    __syncthreads();

    auto stage_ih = [&](int t) {
        if (LAYER == 0) {
#pragma unroll
            for (int it = 0; it < 4; it++) {            // feat cols 0..63 in-register
                int idx = tid + it*256;
                int row = idx >> 3, ch = idx & 7;
                int m = m0s + row;
                float av = d_acc[m*T_STEPS + t] * d_dinv[m];
                uint32_t w[4];
#pragma unroll
                for (int i = 0; i < 4; i++) {
                    int k = ch*8 + 2*i;
                    float f0 = fmaxf(fmaf(av, sgw[k],   sgw[64+k]),   0.f);
                    float f1 = fmaxf(fmaf(av, sgw[k+1], sgw[64+k+1]), 0.f);
                    __nv_bfloat162 b2 = __floats2bfloat162_rn(f0, f1);
                    w[i] = *reinterpret_cast<uint32_t*>(&b2);
                }
                sts128(sb + (uint32_t)((row*KP + ch*8)*2), make_uint4(w[0], w[1], w[2], w[3]));
            }
        } else {
            const __nv_bfloat16* src = d_y0b + (size_t)t*NNV*LH;
#pragma unroll
            for (int it = 0; it < 8; it++) {            // ih cols 0..127 via cp.async
                int idx = tid + it*256;
                int row = idx >> 4, ch = idx & 15;
                cp16(sb + (uint32_t)((row*KP + ch*8)*2), src + (size_t)(m0s + row)*LH + ch*8);
            }
            asm volatile("cp.async.commit_group;");
        }
    };
    auto issueB = [&](int ch, int bsel) {
        const __nv_bfloat16* src = img + ch*64*KP;
        uint32_t dst = sb + OFF_B + bsel*BCH;
        for (int i = tid; i < BCH/16; i += 256) cp16(dst + i*16, src + (size_t)i*8);
        asm volatile("cp.async.commit_group;");
    };

    stage_ih(0);
    issueB(0, 0);

    int buf = 0;
    for (int t = 0; t < T_STEPS; t++) {
        asm volatile("cp.async.wait_group 1;");      // ih for this step done (B0 may pend)
        __syncthreads();                             // h-col epilogue writes visible

        // A fragments for the whole step -> registers (A smem then reusable)
        uint32_t afr[NK16][4];
        uint32_t aAddr = sb + (uint32_t)(((wid*16 + (g & 1)*8 + lr)*KP + (g >> 1)*8)*2);
#pragma unroll
        for (int s = 0; s < NK16; s++)
            ldsm4(aAddr + s*32, afr[s][0], afr[s][1], afr[s][2], afr[s][3]);
        __syncthreads();
        if (t + 1 < T_STEPS) stage_ih(t + 1);        // ih cols dead -> prefetch next step

        for (int ch = 0; ch < 8; ch++) {
            if (!(t == T_STEPS - 1 && ch == 7)) issueB((ch + 1) & 7, buf ^ 1);
            asm volatile("cp.async.wait_group 1;");
            __syncthreads();

            float acc[8][4];
#pragma unroll
            for (int a = 0; a < 8; a++) { acc[a][0]=acc[a][1]=acc[a][2]=acc[a][3]=0.f; }
            uint32_t bbase = sb + OFF_B + buf*BCH
                           + (uint32_t)((((g >> 1)*8 + lr)*KP + (g & 1)*8)*2);
#pragma unroll
            for (int s = 0; s < NK16; s++) {
                uint32_t bB[4][4];
#pragma unroll
                for (int p = 0; p < 4; p++)
                    ldsm4(bbase + (uint32_t)(p*16*KP*2) + s*32, bB[p][0], bB[p][1], bB[p][2], bB[p][3]);
#pragma unroll
                for (int p = 0; p < 4; p++) {
                    mma16816(acc[2*p],   afr[s], &bB[p][0]);
                    mma16816(acc[2*p+1], afr[s], &bB[p][2]);
                }
            }

            // epilogue: in-register gate math via (i,f)/(g,o) pair shuffle
            {
                const bool evn = ((lane & 1) == 0);
                const int rr = wid*16 + (lane >> 2) + (evn ? 0 : 8);
#pragma unroll
                for (int nt = 0; nt < 8; nt++) {
                    float v1 = __shfl_xor_sync(0xffffffffu, evn ? acc[nt][2] : acc[nt][0], 1);
                    float v2 = __shfl_xor_sync(0xffffffffu, evn ? acc[nt][3] : acc[nt][1], 1);
                    float gi = evn ? acc[nt][0] : v1;
                    float gf = evn ? acc[nt][1] : v2;
                    float gg = evn ? v1 : acc[nt][2];
                    float go = evn ? v2 : acc[nt][3];
                    int uu = ch*16 + nt*2 + ((lane & 3) >> 1);
                    const float* b4 = sbias + uu*4;
                    gi += b4[0]; gf += b4[1]; gg += b4[2]; go += b4[3];
                    float cold = cS[rr*129 + uu];
                    float cn = sigmfast(gf)*cold + sigmfast(gi)*tanhfast(gg);
                    cS[rr*129 + uu] = cn;
                    float hv = sigmfast(go)*tanhfast(cn);
                    *(__nv_bfloat16*)(smem + (size_t)(rr*KP + KIH + uu)*2) = __float2bfloat16(hv);
                }
            }
            __syncthreads();
            buf ^= 1;
        }

        // coalesced h tile -> global (y0 for layer0; final h for layer1)
        if (LAYER == 0 || t == T_STEPS - 1) {
            __nv_bfloat16* dst = (LAYER == 0) ? (d_y0b + (size_t)t*NNV*LH) : d_hAb;
#pragma unroll
            for (int it = 0; it < 8; it++) {
                int idx = tid + it*256;
                int row = idx >> 4, c8 = idx & 15;
                uint4 v = *(uint4*)(smem + (size_t)(row*KP + KIH + c8*8)*2);
                *(uint4*)(dst + (size_t)(m0s + row)*LH + c8*8) = v;
            }
        }
    }
}

// ---------------- head: out = x_t + relu(h@pw1^T+pb1)@pw2^T + pb2 ----------------
__global__ void k_head(const __nv_bfloat16* __restrict__ h, const float* __restrict__ x,
                       const float* __restrict__ pw1, const float* __restrict__ pb1,
                       const float* __restrict__ pw2, const float* __restrict__ pb2,
                       float* __restrict__ out, int NN) {
    __shared__ float w1s[128][65];
    __shared__ float w2s[64], b1s[64];
    const int tid = threadIdx.x;
    for (int idx = tid; idx < 64*128; idx += 256) {
        int j = idx >> 7, k = idx & 127;
        w1s[k][j] = pw1[idx];
    }
    if (tid < 64) { w2s[tid] = pw2[tid]; b1s[tid] = pb1[tid]; }
    __syncthreads();

    int warp = tid >> 5, lane = tid & 31;
    int n = blockIdx.x*8 + warp;
    if (n >= NN) return;
    const __nv_bfloat16* hr = h + (size_t)n*LH;
    float s0 = b1s[lane], s1 = b1s[lane+32];
#pragma unroll 8
    for (int k = 0; k < 128; k++) {
        float hv = __bfloat162float(hr[k]);
        s0 = fmaf(hv, w1s[k][lane],    s0);
        s1 = fmaf(hv, w1s[k][lane+32], s1);
    }
    float part = fmaxf(s0, 0.f)*w2s[lane] + fmaxf(s1, 0.f)*w2s[lane+32];
#pragma unroll
    for (int o = 16; o; o >>= 1) part += __shfl_xor_sync(0xffffffffu, part, o);
    if (lane == 0) out[n] = part + pb2[0] + x[n*T_STEPS + (T_STEPS-1)];
}

// ---------------- launcher ----------------
extern "C" void kernel_launch(void* const* d_in, const int* in_sizes, int n_in,
                              void* d_out, int out_size) {
    const float* x    = (const float*)d_in[0];
    const int*   ei   = (const int*)  d_in[1];
    const float* gw   = (const float*)d_in[2];
    const float* gb   = (const float*)d_in[3];
    const float* wih0 = (const float*)d_in[4];
    const float* whh0 = (const float*)d_in[5];
    const float* bih0 = (const float*)d_in[6];
    const float* bhh0 = (const float*)d_in[7];
    const float* wih1 = (const float*)d_in[8];
    const float* whh1 = (const float*)d_in[9];
    const float* bih1 = (const float*)d_in[10];
    const float* bhh1 = (const float*)d_in[11];
    const float* pw1  = (const float*)d_in[12];
    const float* pb1  = (const float*)d_in[13];
    const float* pw2  = (const float*)d_in[14];
    const float* pb2  = (const float*)d_in[15];
    float* out = (float*)d_out;

    const int NN = in_sizes[0] / T_STEPS;   // 16000
    const int E  = in_sizes[1] / 2;         // 256000
    const int* src = ei;
    const int* dst = ei + E;

    float *p_deg, *p_dinv, *p_acc, *p_biasC;
    __nv_bfloat16 *p_hAb, *p_img0, *p_img1;
    cudaGetSymbolAddress((void**)&p_deg,   d_deg);
    cudaGetSymbolAddress((void**)&p_dinv,  d_dinv);
    cudaGetSymbolAddress((void**)&p_acc,   d_acc);
    cudaGetSymbolAddress((void**)&p_biasC, d_biasC);
    cudaGetSymbolAddress((void**)&p_hAb,   d_hAb);
    cudaGetSymbolAddress((void**)&p_img0,  d_img0);
    cudaGetSymbolAddress((void**)&p_img1,  d_img1);

    // dynamic smem: A + c + 2*Bchunk + bias + gwgb
    const int SMB0 = 128*200*2 + 128*129*4 + 2*64*200*2 + 2048 + 512;   // 171008
    const int SMB1 = 128*264*2 + 128*129*4 + 2*64*264*2 + 2048 + 512;   // 203776
    cudaFuncSetAttribute(k_lstm<0>, cudaFuncAttributeMaxDynamicSharedMemorySize, SMB0);
    cudaFuncSetAttribute(k_lstm<1>, cudaFuncAttributeMaxDynamicSharedMemorySize, SMB1);

    // weight images (+ fused deg-init / bias prep)
    k_prepw<<<(512*192 + 255)/256, 256>>>(wih0, whh0, p_img0, 64, 200,
                                          p_deg, NN, bih0, bhh0, p_biasC);
    k_prepw<<<(512*256 + 255)/256, 256>>>(wih1, whh1, p_img1, LH, 264,
                                          nullptr, 0, bih1, bhh1, p_biasC + 512);

    // GCN scalar aggregation
    k_deg_edges   <<<(E/4 + 255)/256, 256>>>(dst, p_deg, E);
    k_dinv_accinit<<<(NN  + 255)/256, 256>>>(x, p_deg, p_dinv, p_acc, NN);
    k_scatter     <<<(E/4 + 255)/256, 256>>>(src, dst, x, p_dinv, p_acc, E);

    // layer 0 then layer 1 (per-CTA independent; kernel boundary syncs y0)
    k_lstm<0><<<NCTA, 256, SMB0>>>(gw, gb);
    k_lstm<1><<<NCTA, 256, SMB1>>>(gw, gb);

    // head + residual
    k_head<<<(NN + 7)/8, 256>>>(p_hAb, x, pw1, pb1, pw2, pb2, out, NN);
}

// round 10
// speedup vs baseline: 5.4827x; 1.0889x over previous
#include <cuda_runtime.h>
#include <cuda_bf16.h>
#include <stdint.h>

#define T_STEPS 5
#define LH 128
#define NNV 16000
#define NCTA 125        // 16000/128

// ---------------- scratch (device globals; no runtime allocation) ----------------
__device__ float d_deg [NNV];
__device__ float d_dinv[NNV];
__device__ float d_acc [NNV*T_STEPS];
__device__ __nv_bfloat16 d_y0b [(size_t)T_STEPS*NNV*LH];   // layer-0 hidden sequence
__device__ __nv_bfloat16 d_hAb [(size_t)NNV*LH];           // final layer-1 h
__device__ __nv_bfloat16 d_img0[512*200];                  // layer0 weight image [j][k], pitch 200
__device__ __nv_bfloat16 d_img1[512*264];                  // layer1, pitch 264
__device__ float d_biasC[1024];                            // [layer][u*4+gate]

// ---------------- helpers ----------------
__device__ __forceinline__ float tanhfast(float x) {
    float y; asm("tanh.approx.f32 %0, %1;" : "=f"(y) : "f"(x)); return y;
}
__device__ __forceinline__ float sigmfast(float x) { return fmaf(tanhfast(0.5f*x), 0.5f, 0.5f); }

__device__ __forceinline__ uint32_t smem_u32(const void* p) {
    uint32_t a;
    asm("{ .reg .u64 t; cvta.to.shared.u64 t, %1; cvt.u32.u64 %0, t; }" : "=r"(a) : "l"(p));
    return a;
}
__device__ __forceinline__ void cp16(uint32_t d, const void* s) {
    asm volatile("cp.async.cg.shared.global [%0], [%1], 16;" :: "r"(d), "l"(s));
}
__device__ __forceinline__ void sts128(uint32_t a, uint4 v) {
    asm volatile("st.shared.v4.b32 [%0], {%1,%2,%3,%4};" :: "r"(a), "r"(v.x), "r"(v.y), "r"(v.z), "r"(v.w) : "memory");
}
__device__ __forceinline__ void ldsm4(uint32_t a, uint32_t& r0, uint32_t& r1, uint32_t& r2, uint32_t& r3) {
    asm volatile("ldmatrix.sync.aligned.m8n8.x4.shared.b16 {%0,%1,%2,%3}, [%4];"
                 : "=r"(r0), "=r"(r1), "=r"(r2), "=r"(r3) : "r"(a));
}
__device__ __forceinline__ void mma16816(float* d, const uint32_t* a, const uint32_t* b) {
    asm volatile("mma.sync.aligned.m16n8k16.row.col.f32.bf16.bf16.f32 "
        "{%0,%1,%2,%3}, {%4,%5,%6,%7}, {%8,%9}, {%0,%1,%2,%3};"
        : "+f"(d[0]), "+f"(d[1]), "+f"(d[2]), "+f"(d[3])
        : "r"(a[0]), "r"(a[1]), "r"(a[2]), "r"(a[3]), "r"(b[0]), "r"(b[1]));
}

// ---------------- GCN scalar pipeline (4-edge ILP) ----------------
__global__ void k_deg_edges(const int* __restrict__ dst, float* deg, int E) {
    int e0 = (blockIdx.x*blockDim.x + threadIdx.x)*4;
#pragma unroll
    for (int j = 0; j < 4; j++) {
        int e = e0 + j;
        if (e < E) atomicAdd(&deg[dst[e]], 1.0f);
    }
}
__global__ void k_dinv_accinit(const float* __restrict__ x, const float* __restrict__ deg,
                               float* __restrict__ dinv, float* __restrict__ acc, int n) {
    int i = blockIdx.x*blockDim.x + threadIdx.x;
    if (i >= n) return;
    float di = rsqrtf(deg[i]);
    dinv[i] = di;
#pragma unroll
    for (int t = 0; t < T_STEPS; t++)
        acc[i*T_STEPS + t] = x[i*T_STEPS + t] * di;
}
__global__ void k_scatter(const int* __restrict__ src, const int* __restrict__ dst,
                          const float* __restrict__ x, const float* __restrict__ dinv,
                          float* __restrict__ acc, int E) {
    int e0 = (blockIdx.x*blockDim.x + threadIdx.x)*4;
#pragma unroll
    for (int j = 0; j < 4; j++) {
        int e = e0 + j;
        if (e < E) {
            int s = src[e], d = dst[e];
            float ds = dinv[s];
#pragma unroll
            for (int t = 0; t < T_STEPS; t++)
                atomicAdd(&acc[d*T_STEPS + t], x[s*T_STEPS + t] * ds);
        }
    }
}

// ---------------- weight/bias pre-transform (both layers, one launch) ----------------
// img[j][k], j = 4*unit + gate (W row = gate*128+unit), k = [ih | hh], pitch KP.
__global__ void k_prepw(const float* __restrict__ Wih0, const float* __restrict__ Whh0,
                        const float* __restrict__ Wih1, const float* __restrict__ Whh1,
                        const float* __restrict__ bi0, const float* __restrict__ bh0,
                        const float* __restrict__ bi1, const float* __restrict__ bh1,
                        float* deg, int nn) {
    int gid = blockIdx.x*256 + threadIdx.x;
    if (gid < nn) deg[gid] = 1.0f;
    if (gid < 1024) {
        int l = gid >> 9, r = gid & 511;
        int u = r >> 2, gt = r & 3;
        d_biasC[gid] = l ? (bi1[gt*LH + u] + bh1[gt*LH + u])
                         : (bi0[gt*LH + u] + bh0[gt*LH + u]);
    }
    const int W0 = 512*192;
    if (gid < W0) {
        int k = gid % 192, j = gid / 192;
        int u = j >> 2, gt = j & 3;
        float v = (k < 64) ? Wih0[(gt*LH + u)*64 + k] : Whh0[(gt*LH + u)*LH + (k - 64)];
        d_img0[j*200 + k] = __float2bfloat16(v);
    } else if (gid < W0 + 512*256) {
        int g2 = gid - W0;
        int k = g2 % 256, j = g2 / 256;
        int u = j >> 2, gt = j & 3;
        float v = (k < 128) ? Wih1[(gt*LH + u)*LH + k] : Whh1[(gt*LH + u)*LH + (k - 128)];
        d_img1[j*264 + k] = __float2bfloat16(v);
    }
}

// ---------------- per-CTA-independent LSTM layer (all 5 steps) --------------------
// CTA owns 128 rows x all 512 gate cols. Warp grid 4 row-groups x 2 col-halves:
// each B fragment loaded by 4 warps (was 8) -> half the smem-port traffic.
// A fragments register-resident per step; h lives in the A-tile h-columns;
// c in smem. B streamed in 64-col double-buffered chunks.
template<int LAYER>
__global__ void __launch_bounds__(256, 1)
k_lstm(const float* __restrict__ gw, const float* __restrict__ gb)
{
    constexpr int KIH  = LAYER ? 128 : 64;
    constexpr int KP   = KIH + LH + 8;          // 264 / 200
    constexpr int NK16 = (KIH + LH) / 16;       // 16 / 12
    constexpr int AB   = 128*KP*2;
    constexpr int CB   = 128*129*4;
    constexpr int BCH  = 64*KP*2;
    constexpr int OFF_C    = AB;
    constexpr int OFF_B    = AB + CB;
    constexpr int OFF_BIAS = OFF_B + 2*BCH;
    constexpr int OFF_GW   = OFF_BIAS + 2048;

    extern __shared__ char smem[];
    const uint32_t sb = smem_u32(smem);
    float* cS    = (float*)(smem + OFF_C);      // [128][129]
    float* sbias = (float*)(smem + OFF_BIAS);   // 512
    float* sgw   = (float*)(smem + OFF_GW);     // 64 gw + 64 gb

    const int tid = threadIdx.x, wid = tid >> 5, lane = tid & 31;
    const int g = lane >> 3, lr = lane & 7;
    const int wr = wid >> 1, wc = wid & 1;      // 4 row-groups x 2 col-halves
    const int m0s = blockIdx.x*128;
    const __nv_bfloat16* img = LAYER ? d_img1 : d_img0;

    if (LAYER == 0 && tid < 128) sgw[tid] = (tid < 64) ? gw[tid] : gb[tid - 64];
    for (int i = tid; i < 512; i += 256) sbias[i] = d_biasC[LAYER*512 + i];
    // zero A tile (h cols = h0 = 0) and c
    for (int i = tid; i < AB/16; i += 256) ((uint4*)smem)[i] = make_uint4(0,0,0,0);
    for (int i = tid; i < CB/16; i += 256) ((uint4*)(smem + OFF_C))[i] = make_uint4(0,0,0,0);
    __syncthreads();

    auto stage_ih = [&](int t) {
        if (LAYER == 0) {
#pragma unroll
            for (int it = 0; it < 4; it++) {            // feat cols 0..63 in-register
                int idx = tid + it*256;
                int row = idx >> 3, ch = idx & 7;
                int m = m0s + row;
                float av = d_acc[m*T_STEPS + t] * d_dinv[m];
                uint32_t w[4];
#pragma unroll
                for (int i = 0; i < 4; i++) {
                    int k = ch*8 + 2*i;
                    float f0 = fmaxf(fmaf(av, sgw[k],   sgw[64+k]),   0.f);
                    float f1 = fmaxf(fmaf(av, sgw[k+1], sgw[64+k+1]), 0.f);
                    __nv_bfloat162 b2 = __floats2bfloat162_rn(f0, f1);
                    w[i] = *reinterpret_cast<uint32_t*>(&b2);
                }
                sts128(sb + (uint32_t)((row*KP + ch*8)*2), make_uint4(w[0], w[1], w[2], w[3]));
            }
        } else {
            const __nv_bfloat16* src = d_y0b + (size_t)t*NNV*LH;
#pragma unroll
            for (int it = 0; it < 8; it++) {            // ih cols 0..127 via cp.async
                int idx = tid + it*256;
                int row = idx >> 4, ch = idx & 15;
                cp16(sb + (uint32_t)((row*KP + ch*8)*2), src + (size_t)(m0s + row)*LH + ch*8);
            }
            asm volatile("cp.async.commit_group;");
        }
    };
    auto issueB = [&](int ch, int bsel) {
        const __nv_bfloat16* src = img + ch*64*KP;
        uint32_t dst = sb + OFF_B + bsel*BCH;
        for (int i = tid; i < BCH/16; i += 256) cp16(dst + i*16, src + (size_t)i*8);
        asm volatile("cp.async.commit_group;");
    };

    stage_ih(0);
    issueB(0, 0);

    int buf = 0;
    for (int t = 0; t < T_STEPS; t++) {
        asm volatile("cp.async.wait_group 1;");      // ih for this step done (B0 may pend)
        __syncthreads();                             // h-col epilogue writes visible

        // A fragments for the whole step -> registers (32 rows per warp, 2 m16-groups)
        uint32_t afr[NK16][8];
        uint32_t aAddr0 = sb + (uint32_t)(((wr*32 + (g & 1)*8 + lr)*KP + (g >> 1)*8)*2);
#pragma unroll
        for (int s = 0; s < NK16; s++) {
            ldsm4(aAddr0 + s*32,                       afr[s][0], afr[s][1], afr[s][2], afr[s][3]);
            ldsm4(aAddr0 + (uint32_t)(16*KP*2) + s*32, afr[s][4], afr[s][5], afr[s][6], afr[s][7]);
        }
        __syncthreads();
        if (t + 1 < T_STEPS) stage_ih(t + 1);        // ih cols dead -> prefetch next step

        for (int ch = 0; ch < 8; ch++) {
            if (!(t == T_STEPS - 1 && ch == 7)) issueB((ch + 1) & 7, buf ^ 1);
            asm volatile("cp.async.wait_group 1;");
            __syncthreads();

            float acc[2][4][4];
#pragma unroll
            for (int mt = 0; mt < 2; mt++)
#pragma unroll
                for (int nt = 0; nt < 4; nt++)
#pragma unroll
                    for (int i = 0; i < 4; i++) acc[mt][nt][i] = 0.f;

            // this warp's 32 cols within the 64-col chunk
            uint32_t bbase = sb + OFF_B + buf*BCH
                           + (uint32_t)(((wc*32 + (g >> 1)*8 + lr)*KP + (g & 1)*8)*2);
#pragma unroll
            for (int s = 0; s < NK16; s++) {
                uint32_t bB[2][4];
#pragma unroll
                for (int p = 0; p < 2; p++)
                    ldsm4(bbase + (uint32_t)(p*16*KP*2) + s*32, bB[p][0], bB[p][1], bB[p][2], bB[p][3]);
#pragma unroll
                for (int p = 0; p < 2; p++) {
                    mma16816(acc[0][2*p],   afr[s],     &bB[p][0]);
                    mma16816(acc[0][2*p+1], afr[s],     &bB[p][2]);
                    mma16816(acc[1][2*p],   afr[s] + 4, &bB[p][0]);
                    mma16816(acc[1][2*p+1], afr[s] + 4, &bB[p][2]);
                }
            }

            // epilogue: in-register gate math via (i,f)/(g,o) pair shuffle
            {
                const bool evn = ((lane & 1) == 0);
#pragma unroll
                for (int mt = 0; mt < 2; mt++) {
                    const int rr = wr*32 + mt*16 + (lane >> 2) + (evn ? 0 : 8);
#pragma unroll
                    for (int nt = 0; nt < 4; nt++) {
                        float v1 = __shfl_xor_sync(0xffffffffu, evn ? acc[mt][nt][2] : acc[mt][nt][0], 1);
                        float v2 = __shfl_xor_sync(0xffffffffu, evn ? acc[mt][nt][3] : acc[mt][nt][1], 1);
                        float gi = evn ? acc[mt][nt][0] : v1;
                        float gf = evn ? acc[mt][nt][1] : v2;
                        float gg = evn ? v1 : acc[mt][nt][2];
                        float go = evn ? v2 : acc[mt][nt][3];
                        int uu = ch*16 + wc*8 + nt*2 + ((lane & 3) >> 1);
                        const float* b4 = sbias + uu*4;
                        gi += b4[0]; gf += b4[1]; gg += b4[2]; go += b4[3];
                        float cold = cS[rr*129 + uu];
                        float cn = sigmfast(gf)*cold + sigmfast(gi)*tanhfast(gg);
                        cS[rr*129 + uu] = cn;
                        float hv = sigmfast(go)*tanhfast(cn);
                        *(__nv_bfloat16*)(smem + (size_t)(rr*KP + KIH + uu)*2) = __float2bfloat16(hv);
                    }
                }
            }
            __syncthreads();
            buf ^= 1;
        }

        // coalesced h tile -> global (y0 for layer0; final h for layer1)
        if (LAYER == 0 || t == T_STEPS - 1) {
            __nv_bfloat16* dst = (LAYER == 0) ? (d_y0b + (size_t)t*NNV*LH) : d_hAb;
#pragma unroll
            for (int it = 0; it < 8; it++) {
                int idx = tid + it*256;
                int row = idx >> 4, c8 = idx & 15;
                uint4 v = *(uint4*)(smem + (size_t)(row*KP + KIH + c8*8)*2);
                *(uint4*)(dst + (size_t)(m0s + row)*LH + c8*8) = v;
            }
        }
    }
}

// ---------------- head: out = x_t + relu(h@pw1^T+pb1)@pw2^T + pb2 ----------------
__global__ void k_head(const __nv_bfloat16* __restrict__ h, const float* __restrict__ x,
                       const float* __restrict__ pw1, const float* __restrict__ pb1,
                       const float* __restrict__ pw2, const float* __restrict__ pb2,
                       float* __restrict__ out, int NN) {
    __shared__ float w1s[128][65];
    __shared__ float w2s[64], b1s[64];
    const int tid = threadIdx.x;
    for (int idx = tid; idx < 64*128; idx += 256) {
        int j = idx >> 7, k = idx & 127;
        w1s[k][j] = pw1[idx];
    }
    if (tid < 64) { w2s[tid] = pw2[tid]; b1s[tid] = pb1[tid]; }
    __syncthreads();

    int warp = tid >> 5, lane = tid & 31;
    int n = blockIdx.x*8 + warp;
    if (n >= NN) return;
    const __nv_bfloat16* hr = h + (size_t)n*LH;
    float s0 = b1s[lane], s1 = b1s[lane+32];
#pragma unroll 8
    for (int k = 0; k < 128; k++) {
        float hv = __bfloat162float(hr[k]);
        s0 = fmaf(hv, w1s[k][lane],    s0);
        s1 = fmaf(hv, w1s[k][lane+32], s1);
    }
    float part = fmaxf(s0, 0.f)*w2s[lane] + fmaxf(s1, 0.f)*w2s[lane+32];
#pragma unroll
    for (int o = 16; o; o >>= 1) part += __shfl_xor_sync(0xffffffffu, part, o);
    if (lane == 0) out[n] = part + pb2[0] + x[n*T_STEPS + (T_STEPS-1)];
}

// ---------------- launcher ----------------
extern "C" void kernel_launch(void* const* d_in, const int* in_sizes, int n_in,
                              void* d_out, int out_size) {
    const float* x    = (const float*)d_in[0];
    const int*   ei   = (const int*)  d_in[1];
    const float* gw   = (const float*)d_in[2];
    const float* gb   = (const float*)d_in[3];
    const float* wih0 = (const float*)d_in[4];
    const float* whh0 = (const float*)d_in[5];
    const float* bih0 = (const float*)d_in[6];
    const float* bhh0 = (const float*)d_in[7];
    const float* wih1 = (const float*)d_in[8];
    const float* whh1 = (const float*)d_in[9];
    const float* bih1 = (const float*)d_in[10];
    const float* bhh1 = (const float*)d_in[11];
    const float* pw1  = (const float*)d_in[12];
    const float* pb1  = (const float*)d_in[13];
    const float* pw2  = (const float*)d_in[14];
    const float* pb2  = (const float*)d_in[15];
    float* out = (float*)d_out;

    const int NN = in_sizes[0] / T_STEPS;   // 16000
    const int E  = in_sizes[1] / 2;         // 256000
    const int* src = ei;
    const int* dst = ei + E;

    float *p_deg, *p_dinv, *p_acc;
    __nv_bfloat16 *p_hAb;
    cudaGetSymbolAddress((void**)&p_deg,  d_deg);
    cudaGetSymbolAddress((void**)&p_dinv, d_dinv);
    cudaGetSymbolAddress((void**)&p_acc,  d_acc);
    cudaGetSymbolAddress((void**)&p_hAb,  d_hAb);

    // dynamic smem: A + c + 2*Bchunk + bias + gwgb
    const int SMB0 = 128*200*2 + 128*129*4 + 2*64*200*2 + 2048 + 512;   // 171008
    const int SMB1 = 128*264*2 + 128*129*4 + 2*64*264*2 + 2048 + 512;   // 203776
    cudaFuncSetAttribute(k_lstm<0>, cudaFuncAttributeMaxDynamicSharedMemorySize, SMB0);
    cudaFuncSetAttribute(k_lstm<1>, cudaFuncAttributeMaxDynamicSharedMemorySize, SMB1);

    // weight/bias images (+ deg-init), single launch
    k_prepw<<<(512*192 + 512*256 + 255)/256, 256>>>(wih0, whh0, wih1, whh1,
                                                    bih0, bhh0, bih1, bhh1, p_deg, NN);

    // GCN scalar aggregation
    k_deg_edges   <<<(E/4 + 255)/256, 256>>>(dst, p_deg, E);
    k_dinv_accinit<<<(NN  + 255)/256, 256>>>(x, p_deg, p_dinv, p_acc, NN);
    k_scatter     <<<(E/4 + 255)/256, 256>>>(src, dst, x, p_dinv, p_acc, E);

    // layer 0 then layer 1 (per-CTA independent; kernel boundary syncs y0)
    k_lstm<0><<<NCTA, 256, SMB0>>>(gw, gb);
    k_lstm<1><<<NCTA, 256, SMB1>>>(gw, gb);

    // head + residual
    k_head<<<(NN + 7)/8, 256>>>(p_hAb, x, pw1, pb1, pw2, pb2, out, NN);
}